// round 8
// baseline (speedup 1.0000x reference)
#include <cuda_runtime.h>
#include <math.h>

#define Nn 4096
#define Ee 262144
#define IND 64
#define Hh 128
#define NHEADS 4
#define DHd 32
#define Ll 2
#define KSPLIT 4
#define NQH (Nn * NHEADS)
#define FLASHBLK ((Nn / 64) * NHEADS * KSPLIT)   // 1024
#define NTILES ((Nn / KSPLIT) / 64)              // 16

typedef unsigned long long ull;

// ---------------- scratch (static device globals; no allocation) -------------
__device__ float g_h[Nn*Hh];
__device__ float g_xp[Nn*Hh];
__device__ float g_als[Nn*NHEADS];
__device__ float g_ald[Nn*NHEADS];
__device__ float g_hloc[Nn*Hh];
__device__ float g_qkv[Nn*3*Hh];
__device__ float g_attn[Nn*Hh];
__device__ float g_out[Nn*Hh];
__device__ float g_t1[Nn*2*Hh];
// flash split-K partials
__device__ float g_pm[KSPLIT*NQH];
__device__ float g_pl[KSPLIT*NQH];
__device__ float g_pacc[KSPLIT*NQH*DHd];
__device__ int   g_tick[256];
// CSR
__device__ int g_cnt[Nn];
__device__ int g_rowptr[Nn+1];
__device__ int g_srcs[Ee];
__device__ int g_bh[64*Nn];

__device__ __forceinline__ float bn_scale(float g) { return g * rsqrtf(1.0f + 1e-5f); }

// ---- f32x2 packed helpers (sm_103a) ----
__device__ __forceinline__ ull pk(float a, float b) {
    ull r; asm("mov.b64 %0,{%1,%2};" : "=l"(r) : "f"(a), "f"(b)); return r;
}
__device__ __forceinline__ void upk(ull v, float& a, float& b) {
    asm("mov.b64 {%0,%1},%2;" : "=f"(a), "=f"(b) : "l"(v));
}
__device__ __forceinline__ ull f2fma(ull a, ull b, ull c) {
    ull d; asm("fma.rn.f32x2 %0,%1,%2,%3;" : "=l"(d) : "l"(a), "l"(b), "l"(c)); return d;
}
__device__ __forceinline__ void cpa16(void* sdst, const void* gsrc) {
    unsigned s = (unsigned)__cvta_generic_to_shared(sdst);
    asm volatile("cp.async.cg.shared.global [%0],[%1],16;" :: "r"(s), "l"(gsrc));
}

// ---- tf32 helpers ----
__device__ __forceinline__ unsigned tf32u(float f) {
    unsigned r; asm("cvt.rna.tf32.f32 %0,%1;" : "=r"(r) : "f"(f)); return r;
}
__device__ __forceinline__ float tf32f(float f) {
    return __uint_as_float(tf32u(f));
}
__device__ __forceinline__ void mma_tf32(float* d, const unsigned* a, unsigned b0, unsigned b1) {
    asm volatile(
        "mma.sync.aligned.m16n8k8.row.col.f32.tf32.tf32.f32 "
        "{%0,%1,%2,%3},{%4,%5,%6,%7},{%8,%9},{%0,%1,%2,%3};"
        : "+f"(d[0]), "+f"(d[1]), "+f"(d[2]), "+f"(d[3])
        : "r"(a[0]), "r"(a[1]), "r"(a[2]), "r"(a[3]), "r"(b0), "r"(b1));
}

// ---------------- tf32 tensor-core GEMM, 64x64 tiles, cp.async pipelined -----
// Requires: Nr = 4096 (grid.y = 64), M1+M2 multiple of 64 (grid.x = Mtot/64),
//           K multiple of 32.
// mode 0: none   1: relu
// mode 2: C1 = epA + (acc+bias + epH) * bn_scale(epG) + epB
// mode 3: C1 = max((epA + acc+bias) * bn_scale(epG) + epB + epH, 0)
__global__ void __launch_bounds__(256) gemm_tf32(
        const float* __restrict__ A,
        const float* __restrict__ B1, const float* __restrict__ bias1,
        float* __restrict__ C1, int M1,
        const float* __restrict__ B2, const float* __restrict__ bias2,
        float* __restrict__ C2, int M2,
        int K, int mode,
        const float* __restrict__ epA, const float* __restrict__ epH,
        const float* __restrict__ epG, const float* __restrict__ epB) {
    __shared__ float As[2][64][36];
    __shared__ float Bs[2][64][36];
    const int t = threadIdx.x;
    const int w = t >> 5, lane = t & 31;
    const int gi = lane >> 2, li = lane & 3;
    const int wr = w >> 2, wc = w & 3;     // 2 x 4 warp grid
    const int r0 = blockIdx.y * 64;
    const int c0 = blockIdx.x * 64;

    const int row_s = t >> 3;              // 0..31 (+32 on second step)
    const int kq4 = (t & 7) * 4;

    float o[2][2][4];
    #pragma unroll
    for (int mt = 0; mt < 2; mt++)
        #pragma unroll
        for (int nt = 0; nt < 2; nt++)
            #pragma unroll
            for (int i = 0; i < 4; i++) o[mt][nt][i] = 0.0f;

    auto stage = [&](int kc, int buf) {
        #pragma unroll
        for (int i = 0; i < 2; i++) {
            int row = row_s + i * 32;
            cpa16(&As[buf][row][kq4], &A[(size_t)(r0 + row) * K + kc + kq4]);
            int cc = c0 + row;
            const float* Brow = (cc < M1) ? (B1 + (size_t)cc * K)
                                          : (B2 + (size_t)(cc - M1) * K);
            cpa16(&Bs[buf][row][kq4], &Brow[kc + kq4]);
        }
        asm volatile("cp.async.commit_group;");
    };

    const int nc = K >> 5;
    stage(0, 0);
    for (int ci = 0; ci < nc; ci++) {
        int buf = ci & 1;
        if (ci + 1 < nc) {
            stage((ci + 1) << 5, buf ^ 1);
            asm volatile("cp.async.wait_group 1;");
        } else {
            asm volatile("cp.async.wait_group 0;");
        }
        __syncthreads();
        #pragma unroll
        for (int k8 = 0; k8 < 32; k8 += 8) {
            unsigned a[2][4];
            #pragma unroll
            for (int mt = 0; mt < 2; mt++) {
                int row = wr * 32 + mt * 16;
                a[mt][0] = tf32u(As[buf][row + gi    ][k8 + li]);
                a[mt][1] = tf32u(As[buf][row + gi + 8][k8 + li]);
                a[mt][2] = tf32u(As[buf][row + gi    ][k8 + li + 4]);
                a[mt][3] = tf32u(As[buf][row + gi + 8][k8 + li + 4]);
            }
            unsigned b[2][2];
            #pragma unroll
            for (int nt = 0; nt < 2; nt++) {
                int col = wc * 16 + nt * 8;
                b[nt][0] = tf32u(Bs[buf][col + gi][k8 + li]);
                b[nt][1] = tf32u(Bs[buf][col + gi][k8 + li + 4]);
            }
            #pragma unroll
            for (int mt = 0; mt < 2; mt++)
                #pragma unroll
                for (int nt = 0; nt < 2; nt++)
                    mma_tf32(o[mt][nt], a[mt], b[nt][0], b[nt][1]);
        }
        __syncthreads();
    }

    // epilogue
    #pragma unroll
    for (int nt = 0; nt < 2; nt++) {
        int c = c0 + wc * 16 + nt * 8 + 2 * li;
        const float* bias; float* Cp; int ld, cc;
        if (c < M1) { bias = bias1; Cp = C1; ld = M1; cc = c; }
        else        { bias = bias2; Cp = C2; ld = M2; cc = c - M1; }
        float b0v = bias ? bias[cc] : 0.0f;
        float b1v = bias ? bias[cc + 1] : 0.0f;
        float gs0 = 0.f, gs1 = 0.f, gb0 = 0.f, gb1 = 0.f;
        if (mode >= 2) {
            gs0 = bn_scale(epG[c]); gs1 = bn_scale(epG[c + 1]);
            gb0 = epB[c]; gb1 = epB[c + 1];
        }
        #pragma unroll
        for (int mt = 0; mt < 2; mt++) {
            #pragma unroll
            for (int half = 0; half < 2; half++) {
                int r = r0 + wr * 32 + mt * 16 + gi + half * 8;
                float v0 = o[mt][nt][half * 2]     + b0v;
                float v1 = o[mt][nt][half * 2 + 1] + b1v;
                if (mode == 1) { v0 = fmaxf(v0, 0.f); v1 = fmaxf(v1, 0.f); }
                else if (mode == 2) {
                    float2 ea = *(const float2*)&epA[(size_t)r * ld + cc];
                    float2 eh = *(const float2*)&epH[(size_t)r * ld + cc];
                    v0 = ea.x + (v0 + eh.x) * gs0 + gb0;
                    v1 = ea.y + (v1 + eh.y) * gs1 + gb1;
                } else if (mode == 3) {
                    float2 ea = *(const float2*)&epA[(size_t)r * ld + cc];
                    float2 eh = *(const float2*)&epH[(size_t)r * ld + cc];
                    v0 = fmaxf((ea.x + v0) * gs0 + gb0 + eh.x, 0.f);
                    v1 = fmaxf((ea.y + v1) * gs1 + gb1 + eh.y, 0.f);
                }
                *(float2*)&Cp[(size_t)r * ld + cc] = make_float2(v0, v1);
            }
        }
    }
}

// ---------------- scalar GEMM (final tiny projection only) -------------------
__global__ void gemm_nt(const float* __restrict__ A,
                        const float* __restrict__ B1, const float* __restrict__ bias1,
                        float* __restrict__ C1, int M1, int Nr, int K) {
    __shared__ float As[16][66];
    __shared__ ull   Bs[16][66];
    const int tx = threadIdx.x, ty = threadIdx.y;
    const int tid = ty * 16 + tx;
    const int r0 = blockIdx.y * 64;
    ull acc[2][4];
    #pragma unroll
    for (int i = 0; i < 2; i++)
        #pragma unroll
        for (int j = 0; j < 4; j++) acc[i][j] = 0ull;

    for (int kt = 0; kt < K; kt += 16) {
        #pragma unroll
        for (int i = 0; i < 4; i++) {
            int idx = tid + i * 256;
            int kk = idx & 15;
            int rr = idx >> 4;
            As[kk][rr] = A[(r0 + rr) * K + kt + kk];
            float bv = (rr < M1) ? B1[(size_t)rr * K + kt + kk] : 0.0f;
            Bs[kk][rr] = pk(bv, bv);
        }
        __syncthreads();
        #pragma unroll
        for (int kk = 0; kk < 16; kk++) {
            ull a01 = *(const ull*)&As[kk][ty * 4];
            ull a23 = *(const ull*)&As[kk][ty * 4 + 2];
            #pragma unroll
            for (int j = 0; j < 4; j++) {
                ull b = Bs[kk][tx + 16 * j];
                acc[0][j] = f2fma(a01, b, acc[0][j]);
                acc[1][j] = f2fma(a23, b, acc[1][j]);
            }
        }
        __syncthreads();
    }
    #pragma unroll
    for (int j = 0; j < 4; j++) {
        int c = tx + 16 * j;
        if (c >= M1) continue;
        float bsv = bias1 ? bias1[c] : 0.0f;
        float v0, v1, v2, v3;
        upk(acc[0][j], v0, v1);
        upk(acc[1][j], v2, v3);
        int r = r0 + ty * 4;
        C1[(size_t)(r + 0) * M1 + c] = v0 + bsv;
        C1[(size_t)(r + 1) * M1 + c] = v1 + bsv;
        C1[(size_t)(r + 2) * M1 + c] = v2 + bsv;
        C1[(size_t)(r + 3) * M1 + c] = v3 + bsv;
    }
}

// ---------------- CSR build (counting sort, no global return-atomics) --------
__global__ void csr_hist(const int* __restrict__ ei) {
    __shared__ int hist[Nn];
    const int t = threadIdx.x;
    for (int i = t; i < Nn; i += 256) hist[i] = 0;
    __syncthreads();
    const int base = blockIdx.x * 4096;
    #pragma unroll 4
    for (int i = t; i < 4096; i += 256)
        atomicAdd(&hist[ei[Ee + base + i]], 1);
    __syncthreads();
    for (int i = t; i < Nn; i += 256) {
        int v = hist[i];
        g_bh[blockIdx.x * Nn + i] = v;
        if (v) atomicAdd(&g_cnt[i], v);
    }
}

__global__ void csr_scan() {
    __shared__ int sm[1024];
    int t = threadIdx.x;
    int b = t * 4;
    int c0 = g_cnt[b], c1 = g_cnt[b+1], c2 = g_cnt[b+2], c3 = g_cnt[b+3];
    int s1 = c0 + c1, s2 = s1 + c2, s3 = s2 + c3;
    sm[t] = s3;
    __syncthreads();
    for (int off = 1; off < 1024; off <<= 1) {
        int v = (t >= off) ? sm[t - off] : 0;
        __syncthreads();
        sm[t] += v;
        __syncthreads();
    }
    int excl = sm[t] - s3;
    g_rowptr[b]   = excl;
    g_rowptr[b+1] = excl + c0;
    g_rowptr[b+2] = excl + s1;
    g_rowptr[b+3] = excl + s2;
    if (t == 1023) g_rowptr[Nn] = sm[1023];
}

// turn per-block hists into per-block base offsets
__global__ void csr_colscan() {
    int i = blockIdx.x * blockDim.x + threadIdx.x;
    if (i >= Nn) return;
    int run = g_rowptr[i];
    #pragma unroll 4
    for (int b = 0; b < 64; b++) {
        int v = g_bh[b * Nn + i];
        g_bh[b * Nn + i] = run;
        run += v;
    }
}

__global__ void csr_scatter(const int* __restrict__ ei) {
    __shared__ int cur[Nn];
    const int t = threadIdx.x;
    const int b = blockIdx.x;
    for (int i = t; i < Nn; i += 256) cur[i] = g_bh[b * Nn + i];
    __syncthreads();
    const int base = b * 4096;
    for (int j = t; j < 4096; j += 256) {
        int d = ei[Ee + base + j];
        int pos = atomicAdd(&cur[d], 1);
        g_srcs[pos] = ei[base + j];
    }
}

// ---------------- GAT: per-node attention logits (+ tick reset) --------------
__global__ void att_logits(const float* __restrict__ asrc, const float* __restrict__ adst) {
    int i = blockIdx.x * blockDim.x + threadIdx.x;
    if (i < 256) g_tick[i] = 0;
    if (i >= Nn * NHEADS) return;
    int n = i >> 2, hd = i & 3;
    const float4* xp = (const float4*)&g_xp[n * Hh + hd * DHd];
    const float4* as = (const float4*)&asrc[hd * DHd];
    const float4* ad = (const float4*)&adst[hd * DHd];
    float s = 0.0f, t = 0.0f;
    #pragma unroll
    for (int d4 = 0; d4 < 8; d4++) {
        float4 v = xp[d4], a = as[d4], b = ad[d4];
        s += v.x*a.x + v.y*a.y + v.z*a.z + v.w*a.w;
        t += v.x*b.x + v.y*b.y + v.z*b.z + v.w*b.w;
    }
    g_als[i] = s;
    g_ald[i] = t;
}

__device__ __forceinline__ float leaky(float x) { return x >= 0.0f ? x : 0.2f * x; }

struct FlashSmem {
    float Ks[64][36];
    float Vs[64][40];
    float Ps[4][16][68];
};

// ---------------- FAT kernel: blocks [0,1024) = flash, [1024,5120) = GAT -----
__global__ void __launch_bounds__(128) gat_flash(
        const float* __restrict__ bias, const float* __restrict__ g0,
        const float* __restrict__ b0) {
    __shared__ FlashSmem sm;
    __shared__ int s_last;
    const int t = threadIdx.x;
    const float NEGINF = -__int_as_float(0x7f800000);

    if (blockIdx.x < FLASHBLK) {
        const int fb = blockIdx.x;
        const int qt = fb & 63;
        const int hd = (fb >> 6) & 3;
        const int sp = fb >> 8;
        const int w = t >> 5, lane = t & 31;
        const int gi = lane >> 2, li = lane & 3;
        const int q0 = qt * 64 + w * 16;
        const int kbase = sp * (Nn / KSPLIT);

        unsigned qa[4][4];
        {
            const float scq = 0.17677669529663687f;
            #pragma unroll
            for (int ks = 0; ks < 4; ks++) {
                int c = hd * 32 + ks * 8 + li;
                qa[ks][0] = tf32u(g_qkv[(q0+gi  )*384 + c] * scq);
                qa[ks][1] = tf32u(g_qkv[(q0+gi+8)*384 + c] * scq);
                qa[ks][2] = tf32u(g_qkv[(q0+gi  )*384 + c+4] * scq);
                qa[ks][3] = tf32u(g_qkv[(q0+gi+8)*384 + c+4] * scq);
            }
        }

        float4 kst[4], vst[4];
        auto ldg_tile = [&](int ti) {
            int kb = kbase + ti * 64;
            #pragma unroll
            for (int i = 0; i < 4; i++) {
                int c = t + i * 128;
                int j = c >> 3, d4 = c & 7;
                const float4* p = (const float4*)&g_qkv[(kb + j) * 384 + 128 + hd * 32 + d4 * 4];
                kst[i] = p[0];
                vst[i] = p[32];
            }
        };
        auto sts_tile = [&]() {
            #pragma unroll
            for (int i = 0; i < 4; i++) {
                int c = t + i * 128;
                int j = c >> 3, d4 = c & 7;
                float4 k4 = kst[i], v4 = vst[i];
                k4.x = tf32f(k4.x); k4.y = tf32f(k4.y); k4.z = tf32f(k4.z); k4.w = tf32f(k4.w);
                v4.x = tf32f(v4.x); v4.y = tf32f(v4.y); v4.z = tf32f(v4.z); v4.w = tf32f(v4.w);
                *(float4*)&sm.Ks[j][d4 * 4] = k4;
                *(float4*)&sm.Vs[j][d4 * 4] = v4;
            }
        };

        float mxl = NEGINF, mxh = NEGINF, lsl = 0.0f, lsh = 0.0f;
        float o[4][4];
        #pragma unroll
        for (int jn = 0; jn < 4; jn++)
            #pragma unroll
            for (int i = 0; i < 4; i++) o[jn][i] = 0.0f;

        ldg_tile(0);
        for (int ti = 0; ti < NTILES; ti++) {
            __syncthreads();
            sts_tile();
            if (ti + 1 < NTILES) ldg_tile(ti + 1);
            __syncthreads();

            float s[8][4];
            #pragma unroll
            for (int jk = 0; jk < 8; jk++) {
                s[jk][0] = s[jk][1] = s[jk][2] = s[jk][3] = 0.0f;
                #pragma unroll
                for (int ks = 0; ks < 4; ks++) {
                    unsigned b0v = __float_as_uint(sm.Ks[jk*8+gi][ks*8+li]);
                    unsigned b1v = __float_as_uint(sm.Ks[jk*8+gi][ks*8+li+4]);
                    mma_tf32(s[jk], qa[ks], b0v, b1v);
                }
            }
            float tml = NEGINF, tmh = NEGINF;
            #pragma unroll
            for (int jk = 0; jk < 8; jk++) {
                tml = fmaxf(tml, fmaxf(s[jk][0], s[jk][1]));
                tmh = fmaxf(tmh, fmaxf(s[jk][2], s[jk][3]));
            }
            tml = fmaxf(tml, __shfl_xor_sync(0xffffffffu, tml, 1));
            tml = fmaxf(tml, __shfl_xor_sync(0xffffffffu, tml, 2));
            tmh = fmaxf(tmh, __shfl_xor_sync(0xffffffffu, tmh, 1));
            tmh = fmaxf(tmh, __shfl_xor_sync(0xffffffffu, tmh, 2));
            float nml = fmaxf(mxl, tml), nmh = fmaxf(mxh, tmh);
            float scl = __expf(mxl - nml), sch = __expf(mxh - nmh);
            mxl = nml; mxh = nmh;
            lsl *= scl; lsh *= sch;
            #pragma unroll
            for (int jn = 0; jn < 4; jn++) {
                o[jn][0] *= scl; o[jn][1] *= scl;
                o[jn][2] *= sch; o[jn][3] *= sch;
            }
            float rsl = 0.0f, rsh = 0.0f;
            #pragma unroll
            for (int jk = 0; jk < 8; jk++) {
                float p0 = __expf(s[jk][0] - mxl), p1 = __expf(s[jk][1] - mxl);
                float p2 = __expf(s[jk][2] - mxh), p3 = __expf(s[jk][3] - mxh);
                rsl += p0 + p1; rsh += p2 + p3;
                float2 lo = make_float2(tf32f(p0), tf32f(p1));
                float2 hi = make_float2(tf32f(p2), tf32f(p3));
                *(float2*)&sm.Ps[w][gi  ][jk*8 + 2*li] = lo;
                *(float2*)&sm.Ps[w][gi+8][jk*8 + 2*li] = hi;
            }
            rsl += __shfl_xor_sync(0xffffffffu, rsl, 1);
            rsl += __shfl_xor_sync(0xffffffffu, rsl, 2);
            rsh += __shfl_xor_sync(0xffffffffu, rsh, 1);
            rsh += __shfl_xor_sync(0xffffffffu, rsh, 2);
            lsl += rsl; lsh += rsh;
            __syncwarp();
            #pragma unroll
            for (int kk = 0; kk < 8; kk++) {
                unsigned pa[4];
                pa[0] = __float_as_uint(sm.Ps[w][gi  ][kk*8 + li]);
                pa[1] = __float_as_uint(sm.Ps[w][gi+8][kk*8 + li]);
                pa[2] = __float_as_uint(sm.Ps[w][gi  ][kk*8 + li + 4]);
                pa[3] = __float_as_uint(sm.Ps[w][gi+8][kk*8 + li + 4]);
                #pragma unroll
                for (int jn = 0; jn < 4; jn++) {
                    unsigned b0v = __float_as_uint(sm.Vs[kk*8+li  ][jn*8+gi]);
                    unsigned b1v = __float_as_uint(sm.Vs[kk*8+li+4][jn*8+gi]);
                    mma_tf32(o[jn], pa, b0v, b1v);
                }
            }
            __syncwarp();
        }

        const int nl = q0 + gi, nh = nl + 8;
        const int qhl = nl * 4 + hd, qhh = nh * 4 + hd;
        if (li == 0) {
            g_pm[sp * NQH + qhl] = mxl;
            g_pl[sp * NQH + qhl] = lsl;
            g_pm[sp * NQH + qhh] = mxh;
            g_pl[sp * NQH + qhh] = lsh;
        }
        #pragma unroll
        for (int jn = 0; jn < 4; jn++) {
            int dh = jn * 8 + 2 * li;
            *(float2*)&g_pacc[((size_t)sp * NQH + qhl) * DHd + dh] = make_float2(o[jn][0], o[jn][1]);
            *(float2*)&g_pacc[((size_t)sp * NQH + qhh) * DHd + dh] = make_float2(o[jn][2], o[jn][3]);
        }

        // ---- fused split-K merge: last block for (qt,hd) merges its 64 queries
        __threadfence();
        if (t == 0) {
            int v = atomicAdd(&g_tick[(qt << 2) | hd], 1);
            s_last = (v == KSPLIT - 1);
        }
        __syncthreads();
        if (s_last) {
            for (int i = t; i < 64 * DHd; i += 128) {
                int q = i >> 5, dd = i & 31;
                int n = qt * 64 + q;
                int qh = n * 4 + hd;
                float m0 = g_pm[0*NQH+qh], m1 = g_pm[1*NQH+qh];
                float m2 = g_pm[2*NQH+qh], m3 = g_pm[3*NQH+qh];
                float M = fmaxf(fmaxf(m0, m1), fmaxf(m2, m3));
                float w0 = __expf(m0 - M), w1 = __expf(m1 - M);
                float w2 = __expf(m2 - M), w3 = __expf(m3 - M);
                float L = g_pl[0*NQH+qh]*w0 + g_pl[1*NQH+qh]*w1
                        + g_pl[2*NQH+qh]*w2 + g_pl[3*NQH+qh]*w3;
                float a = g_pacc[((size_t)0*NQH+qh)*DHd + dd] * w0
                        + g_pacc[((size_t)1*NQH+qh)*DHd + dd] * w1
                        + g_pacc[((size_t)2*NQH+qh)*DHd + dd] * w2
                        + g_pacc[((size_t)3*NQH+qh)*DHd + dd] * w3;
                g_attn[n * Hh + hd * DHd + dd] = a / L;
            }
        }
    } else {
        // =========== GAT aggregation: warp w = head w, lane = channel ===========
        const int d = blockIdx.x - FLASHBLK;
        const int w = t >> 5, lane = t & 31;
        const int beg = g_rowptr[d], end = g_rowptr[d + 1];
        const float adh = g_ald[d * 4 + w];

        float mx = NEGINF;
        for (int e = beg + lane; e < end; e += 32) {
            int s = g_srcs[e];
            mx = fmaxf(mx, leaky(g_als[s * 4 + w] + adh));
        }
        #pragma unroll
        for (int off = 16; off > 0; off >>= 1)
            mx = fmaxf(mx, __shfl_xor_sync(0xffffffffu, mx, off));

        float den = 0.0f;
        float acc = 0.0f;
        const int c = w * 32 + lane;
        for (int cb = beg; cb < end; cb += 32) {
            int cnt = min(32, end - cb);
            int e = cb + lane;
            float wgt = 0.0f;
            int ssrc = 0;
            if (lane < cnt) {
                ssrc = g_srcs[e];
                wgt = __expf(leaky(g_als[ssrc * 4 + w] + adh) - mx);
            }
            den += wgt;
            for (int j = 0; j < cnt; j++) {
                float wj = __shfl_sync(0xffffffffu, wgt, j);
                int sj   = __shfl_sync(0xffffffffu, ssrc, j);
                acc = fmaf(wj, g_xp[sj * Hh + c], acc);
            }
        }
        #pragma unroll
        for (int off = 16; off > 0; off >>= 1)
            den += __shfl_xor_sync(0xffffffffu, den, off);

        float v = acc / (den + 1e-16f) + bias[c] + g_h[d * Hh + c];
        g_hloc[d * Hh + c] = v * bn_scale(g0[c]) + b0[c];
    }
}

// ---------------- host launch ----------------
extern "C" void kernel_launch(void* const* d_in, const int* in_sizes, int n_in,
                              void* d_out, int out_size) {
    const float* x       = (const float*)d_in[0];
    const int*   ei      = (const int*)d_in[1];
    const float* w_in    = (const float*)d_in[2];
    const float* b_in    = (const float*)d_in[3];
    const float* w_gat   = (const float*)d_in[4];
    const float* att_src = (const float*)d_in[5];
    const float* att_dst = (const float*)d_in[6];
    const float* b_gat   = (const float*)d_in[7];
    const float* w_qkv   = (const float*)d_in[8];
    const float* b_qkv   = (const float*)d_in[9];
    const float* w_o     = (const float*)d_in[10];
    const float* b_o     = (const float*)d_in[11];
    const float* bn_g    = (const float*)d_in[12];
    const float* bn_b    = (const float*)d_in[13];
    const float* w1      = (const float*)d_in[14];
    const float* b1      = (const float*)d_in[15];
    const float* w2      = (const float*)d_in[16];
    const float* b2      = (const float*)d_in[17];
    const float* w_out   = (const float*)d_in[18];
    const float* b_out   = (const float*)d_in[19];
    float* out = (float*)d_out;

    float *p_h, *p_xp, *p_qkv, *p_attn, *p_out, *p_t1, *p_hloc;
    int* p_cnt;
    cudaGetSymbolAddress((void**)&p_h,    g_h);
    cudaGetSymbolAddress((void**)&p_xp,   g_xp);
    cudaGetSymbolAddress((void**)&p_qkv,  g_qkv);
    cudaGetSymbolAddress((void**)&p_attn, g_attn);
    cudaGetSymbolAddress((void**)&p_out,  g_out);
    cudaGetSymbolAddress((void**)&p_t1,   g_t1);
    cudaGetSymbolAddress((void**)&p_hloc, g_hloc);
    cudaGetSymbolAddress((void**)&p_cnt,  g_cnt);

    // CSR build (counting sort)
    cudaMemsetAsync(p_cnt, 0, Nn * sizeof(int));
    csr_hist<<<Ee / 4096, 256>>>(ei);
    csr_scan<<<1, 1024>>>();
    csr_colscan<<<(Nn + 255) / 256, 256>>>();
    csr_scatter<<<Ee / 4096, 256>>>(ei);

    // input projection: h = relu(x @ w_in^T + b_in)
    gemm_tf32<<<dim3(2, 64), 256>>>(x, w_in, b_in, p_h, Hh,
                                    nullptr, nullptr, nullptr, 0, IND, 1,
                                    nullptr, nullptr, nullptr, nullptr);

    for (int l = 0; l < Ll; l++) {
        // fused GAT projection + QKV projection
        gemm_tf32<<<dim3(8, 64), 256>>>(p_h,
                                        w_gat + l * Hh * Hh, nullptr, p_xp, Hh,
                                        w_qkv + l * 3 * Hh * Hh, b_qkv + l * 3 * Hh, p_qkv, 3 * Hh,
                                        Hh, 0, nullptr, nullptr, nullptr, nullptr);
        att_logits<<<(Nn * NHEADS + 127) / 128, 128>>>(att_src + l * Hh, att_dst + l * Hh);

        // FAT kernel: flash attention (split-K merge fused) + GAT aggregation
        gat_flash<<<FLASHBLK + Nn, 128>>>(b_gat + l * Hh,
                                          bn_g + (l * 3 + 0) * Hh, bn_b + (l * 3 + 0) * Hh);

        // w_o GEMM with fused combine_att epilogue -> g_out
        gemm_tf32<<<dim3(2, 64), 256>>>(p_attn, w_o + l * Hh * Hh, b_o + l * Hh, p_out, Hh,
                                        nullptr, nullptr, nullptr, 0, Hh, 2,
                                        p_hloc, p_h,
                                        bn_g + (l * 3 + 1) * Hh, bn_b + (l * 3 + 1) * Hh);

        // MLP
        gemm_tf32<<<dim3(4, 64), 256>>>(p_out, w1 + l * 2 * Hh * Hh, b1 + l * 2 * Hh, p_t1, 2 * Hh,
                                        nullptr, nullptr, nullptr, 0, Hh, 1,
                                        nullptr, nullptr, nullptr, nullptr);
        // w2 GEMM with fused final_combine epilogue -> g_h
        gemm_tf32<<<dim3(2, 64), 256>>>(p_t1, w2 + l * 2 * Hh * Hh, b2 + l * Hh, p_h, Hh,
                                        nullptr, nullptr, nullptr, 0, 2 * Hh, 3,
                                        p_out, p_h,
                                        bn_g + (l * 3 + 2) * Hh, bn_b + (l * 3 + 2) * Hh);
    }

    // output projection -> [4096, 2] (scalar path, M=2)
    gemm_nt<<<dim3(1, 64), dim3(16, 16)>>>(p_h, w_out, b_out, out, 2, Nn, Hh);
}

// round 9
// speedup vs baseline: 1.0556x; 1.0556x over previous
#include <cuda_runtime.h>
#include <math.h>

#define Nn 4096
#define Ee 262144
#define IND 64
#define Hh 128
#define NHEADS 4
#define DHd 32
#define Ll 2
#define KSPLIT 4
#define NQH (Nn * NHEADS)
#define FLASHBLK ((Nn / 64) * NHEADS * KSPLIT)   // 1024
#define NTILES ((Nn / KSPLIT) / 64)              // 16

typedef unsigned long long ull;

// ---------------- scratch (static device globals; no allocation) -------------
__device__ float g_h[Nn*Hh];
__device__ float g_xp[Nn*Hh];
__device__ float g_als[Nn*NHEADS];
__device__ float g_ald[Nn*NHEADS];
__device__ float g_hloc[Nn*Hh];
__device__ float g_qkv[Nn*3*Hh];
__device__ float g_attn[Nn*Hh];
__device__ float g_out[Nn*Hh];
__device__ float g_t1[Nn*2*Hh];
// flash split-K partials
__device__ float g_pm[KSPLIT*NQH];
__device__ float g_pl[KSPLIT*NQH];
__device__ float g_pacc[KSPLIT*NQH*DHd];
__device__ int   g_tick[256];
// CSR
__device__ int g_cnt[Nn];
__device__ int g_cursor[Nn];
__device__ int g_rowptr[Nn+1];
__device__ int g_srcs[Ee];

__device__ __forceinline__ float bn_scale(float g) { return g * rsqrtf(1.0f + 1e-5f); }

// ---- f32x2 packed helpers (sm_103a) ----
__device__ __forceinline__ ull pk(float a, float b) {
    ull r; asm("mov.b64 %0,{%1,%2};" : "=l"(r) : "f"(a), "f"(b)); return r;
}
__device__ __forceinline__ void upk(ull v, float& a, float& b) {
    asm("mov.b64 {%0,%1},%2;" : "=f"(a), "=f"(b) : "l"(v));
}
__device__ __forceinline__ ull f2fma(ull a, ull b, ull c) {
    ull d; asm("fma.rn.f32x2 %0,%1,%2,%3;" : "=l"(d) : "l"(a), "l"(b), "l"(c)); return d;
}
__device__ __forceinline__ void cpa16(void* sdst, const void* gsrc) {
    unsigned s = (unsigned)__cvta_generic_to_shared(sdst);
    asm volatile("cp.async.cg.shared.global [%0],[%1],16;" :: "r"(s), "l"(gsrc));
}
__device__ __forceinline__ float ex2(float x) {
    float r; asm("ex2.approx.f32 %0,%1;" : "=f"(r) : "f"(x)); return r;
}

// ---- tf32 helpers ----
__device__ __forceinline__ unsigned tf32u(float f) {
    unsigned r; asm("cvt.rna.tf32.f32 %0,%1;" : "=r"(r) : "f"(f)); return r;
}
__device__ __forceinline__ float tf32f(float f) {
    return __uint_as_float(tf32u(f));
}
__device__ __forceinline__ void mma_tf32(float* d, const unsigned* a, unsigned b0, unsigned b1) {
    asm volatile(
        "mma.sync.aligned.m16n8k8.row.col.f32.tf32.tf32.f32 "
        "{%0,%1,%2,%3},{%4,%5,%6,%7},{%8,%9},{%0,%1,%2,%3};"
        : "+f"(d[0]), "+f"(d[1]), "+f"(d[2]), "+f"(d[3])
        : "r"(a[0]), "r"(a[1]), "r"(a[2]), "r"(a[3]), "r"(b0), "r"(b1));
}

// ---------------- tf32 GEMM core (64x64 tile, cp.async double-buffered) ------
// mode 0: none  1: relu
// mode 2: C1 = epA + (acc+bias + epH) * bn_scale(epG) + epB
// mode 3: C1 = max((epA + acc+bias) * bn_scale(epG) + epB + epH, 0)
__device__ __forceinline__ void gemm_core(
        float (*As)[64][36], float (*Bs)[64][36], int bx, int by,
        const float* __restrict__ A,
        const float* __restrict__ B1, const float* __restrict__ bias1,
        float* __restrict__ C1, int M1,
        const float* __restrict__ B2, const float* __restrict__ bias2,
        float* __restrict__ C2, int M2,
        int K, int mode,
        const float* __restrict__ epA, const float* __restrict__ epH,
        const float* __restrict__ epG, const float* __restrict__ epB) {
    const int t = threadIdx.x;
    const int w = t >> 5, lane = t & 31;
    const int gi = lane >> 2, li = lane & 3;
    const int wr = w >> 2, wc = w & 3;
    const int r0 = by * 64;
    const int c0 = bx * 64;
    const int row_s = t >> 3;
    const int kq4 = (t & 7) * 4;

    float o[2][2][4];
    #pragma unroll
    for (int mt = 0; mt < 2; mt++)
        #pragma unroll
        for (int nt = 0; nt < 2; nt++)
            #pragma unroll
            for (int i = 0; i < 4; i++) o[mt][nt][i] = 0.0f;

    auto stage = [&](int kc, int buf) {
        #pragma unroll
        for (int i = 0; i < 2; i++) {
            int row = row_s + i * 32;
            cpa16(&As[buf][row][kq4], &A[(size_t)(r0 + row) * K + kc + kq4]);
            int cc = c0 + row;
            const float* Brow = (cc < M1) ? (B1 + (size_t)cc * K)
                                          : (B2 + (size_t)(cc - M1) * K);
            cpa16(&Bs[buf][row][kq4], &Brow[kc + kq4]);
        }
        asm volatile("cp.async.commit_group;");
    };

    const int nc = K >> 5;
    stage(0, 0);
    for (int ci = 0; ci < nc; ci++) {
        int buf = ci & 1;
        if (ci + 1 < nc) {
            stage((ci + 1) << 5, buf ^ 1);
            asm volatile("cp.async.wait_group 1;");
        } else {
            asm volatile("cp.async.wait_group 0;");
        }
        __syncthreads();
        #pragma unroll
        for (int k8 = 0; k8 < 32; k8 += 8) {
            unsigned a[2][4];
            #pragma unroll
            for (int mt = 0; mt < 2; mt++) {
                int row = wr * 32 + mt * 16;
                a[mt][0] = tf32u(As[buf][row + gi    ][k8 + li]);
                a[mt][1] = tf32u(As[buf][row + gi + 8][k8 + li]);
                a[mt][2] = tf32u(As[buf][row + gi    ][k8 + li + 4]);
                a[mt][3] = tf32u(As[buf][row + gi + 8][k8 + li + 4]);
            }
            unsigned b[2][2];
            #pragma unroll
            for (int nt = 0; nt < 2; nt++) {
                int col = wc * 16 + nt * 8;
                b[nt][0] = tf32u(Bs[buf][col + gi][k8 + li]);
                b[nt][1] = tf32u(Bs[buf][col + gi][k8 + li + 4]);
            }
            #pragma unroll
            for (int mt = 0; mt < 2; mt++)
                #pragma unroll
                for (int nt = 0; nt < 2; nt++)
                    mma_tf32(o[mt][nt], a[mt], b[nt][0], b[nt][1]);
        }
        __syncthreads();
    }

    #pragma unroll
    for (int nt = 0; nt < 2; nt++) {
        int c = c0 + wc * 16 + nt * 8 + 2 * li;
        const float* bias; float* Cp; int ld, cc;
        if (c < M1) { bias = bias1; Cp = C1; ld = M1; cc = c; }
        else        { bias = bias2; Cp = C2; ld = M2; cc = c - M1; }
        float b0v = bias ? bias[cc] : 0.0f;
        float b1v = bias ? bias[cc + 1] : 0.0f;
        float gs0 = 0.f, gs1 = 0.f, gb0 = 0.f, gb1 = 0.f;
        if (mode >= 2) {
            gs0 = bn_scale(epG[c]); gs1 = bn_scale(epG[c + 1]);
            gb0 = epB[c]; gb1 = epB[c + 1];
        }
        #pragma unroll
        for (int mt = 0; mt < 2; mt++) {
            #pragma unroll
            for (int half = 0; half < 2; half++) {
                int r = r0 + wr * 32 + mt * 16 + gi + half * 8;
                float v0 = o[mt][nt][half * 2]     + b0v;
                float v1 = o[mt][nt][half * 2 + 1] + b1v;
                if (mode == 1) { v0 = fmaxf(v0, 0.f); v1 = fmaxf(v1, 0.f); }
                else if (mode == 2) {
                    float2 ea = *(const float2*)&epA[(size_t)r * ld + cc];
                    float2 eh = *(const float2*)&epH[(size_t)r * ld + cc];
                    v0 = ea.x + (v0 + eh.x) * gs0 + gb0;
                    v1 = ea.y + (v1 + eh.y) * gs1 + gb1;
                } else if (mode == 3) {
                    float2 ea = *(const float2*)&epA[(size_t)r * ld + cc];
                    float2 eh = *(const float2*)&epH[(size_t)r * ld + cc];
                    v0 = fmaxf((ea.x + v0) * gs0 + gb0 + eh.x, 0.f);
                    v1 = fmaxf((ea.y + v1) * gs1 + gb1 + eh.y, 0.f);
                }
                *(float2*)&Cp[(size_t)r * ld + cc] = make_float2(v0, v1);
            }
        }
    }
}

// standalone tf32 GEMM
__global__ void __launch_bounds__(256) gemm_tf32(
        const float* __restrict__ A,
        const float* __restrict__ B1, const float* __restrict__ bias1,
        float* __restrict__ C1, int M1,
        const float* __restrict__ B2, const float* __restrict__ bias2,
        float* __restrict__ C2, int M2,
        int K, int mode,
        const float* __restrict__ epA, const float* __restrict__ epH,
        const float* __restrict__ epG, const float* __restrict__ epB) {
    __shared__ float As[2][64][36];
    __shared__ float Bs[2][64][36];
    gemm_core(As, Bs, blockIdx.x, blockIdx.y, A, B1, bias1, C1, M1,
              B2, bias2, C2, M2, K, mode, epA, epH, epG, epB);
}

// fused: blocks [0,128) input GEMM (grid 2x64), blocks [128,192) CSR hist
__global__ void __launch_bounds__(256) fused_ingemm_hist(
        const int* __restrict__ ei,
        const float* __restrict__ x,
        const float* __restrict__ w_in, const float* __restrict__ b_in,
        float* __restrict__ C) {
    __shared__ __align__(16) char smbuf[2 * 64 * 36 * 4 * 2];
    const int t = threadIdx.x;
    if (blockIdx.x < 128) {
        float (*As)[64][36] = (float(*)[64][36])smbuf;
        float (*Bs)[64][36] = (float(*)[64][36])(smbuf + 2 * 64 * 36 * 4);
        gemm_core(As, Bs, blockIdx.x & 1, blockIdx.x >> 1, x, w_in, b_in, C, Hh,
                  nullptr, nullptr, nullptr, 0, IND, 1,
                  nullptr, nullptr, nullptr, nullptr);
    } else {
        int* hist = (int*)smbuf;
        for (int i = t; i < Nn; i += 256) hist[i] = 0;
        __syncthreads();
        const int base = (blockIdx.x - 128) * 4096;
        #pragma unroll 4
        for (int i = t; i < 4096; i += 256)
            atomicAdd(&hist[ei[Ee + base + i]], 1);
        __syncthreads();
        for (int i = t; i < Nn; i += 256) {
            int v = hist[i];
            if (v) atomicAdd(&g_cnt[i], v);
        }
    }
}

// fused: blocks [0,512) layer-0 GAT+QKV GEMM (grid 8x64), blocks [512,1536) scatter
__global__ void __launch_bounds__(256) fused_qkvgemm_scatter(
        const int* __restrict__ ei,
        const float* __restrict__ A,
        const float* __restrict__ w_gat,
        const float* __restrict__ w_qkv, const float* __restrict__ b_qkv,
        float* __restrict__ Cxp, float* __restrict__ Cqkv) {
    __shared__ float As[2][64][36];
    __shared__ float Bs[2][64][36];
    if (blockIdx.x < 512) {
        gemm_core(As, Bs, blockIdx.x & 7, blockIdx.x >> 3, A,
                  w_gat, nullptr, Cxp, Hh,
                  w_qkv, b_qkv, Cqkv, 3 * Hh,
                  Hh, 0, nullptr, nullptr, nullptr, nullptr);
    } else {
        int e = (blockIdx.x - 512) * 256 + threadIdx.x;
        if (e < Ee) {
            int d = ei[Ee + e];
            int pos = atomicAdd(&g_cursor[d], 1);
            g_srcs[pos] = ei[e];
        }
    }
}

// standalone scatter (layer-independent; only used via fused kernel)
__global__ void csr_scan() {
    __shared__ int sm[1024];
    int t = threadIdx.x;
    int b = t * 4;
    int c0 = g_cnt[b], c1 = g_cnt[b+1], c2 = g_cnt[b+2], c3 = g_cnt[b+3];
    int s1 = c0 + c1, s2 = s1 + c2, s3 = s2 + c3;
    sm[t] = s3;
    __syncthreads();
    for (int off = 1; off < 1024; off <<= 1) {
        int v = (t >= off) ? sm[t - off] : 0;
        __syncthreads();
        sm[t] += v;
        __syncthreads();
    }
    int excl = sm[t] - s3;
    g_rowptr[b]   = excl;
    g_rowptr[b+1] = excl + c0;
    g_rowptr[b+2] = excl + s1;
    g_rowptr[b+3] = excl + s2;
    g_cursor[b]   = excl;
    g_cursor[b+1] = excl + c0;
    g_cursor[b+2] = excl + s1;
    g_cursor[b+3] = excl + s2;
    if (t == 1023) g_rowptr[Nn] = sm[1023];
}

// ---------------- scalar GEMM (final tiny projection only) -------------------
__global__ void gemm_nt(const float* __restrict__ A,
                        const float* __restrict__ B1, const float* __restrict__ bias1,
                        float* __restrict__ C1, int M1, int Nr, int K) {
    __shared__ float As[16][66];
    __shared__ ull   Bs[16][66];
    const int tx = threadIdx.x, ty = threadIdx.y;
    const int tid = ty * 16 + tx;
    const int r0 = blockIdx.y * 64;
    ull acc[2][4];
    #pragma unroll
    for (int i = 0; i < 2; i++)
        #pragma unroll
        for (int j = 0; j < 4; j++) acc[i][j] = 0ull;

    for (int kt = 0; kt < K; kt += 16) {
        #pragma unroll
        for (int i = 0; i < 4; i++) {
            int idx = tid + i * 256;
            int kk = idx & 15;
            int rr = idx >> 4;
            As[kk][rr] = A[(r0 + rr) * K + kt + kk];
            float bv = (rr < M1) ? B1[(size_t)rr * K + kt + kk] : 0.0f;
            Bs[kk][rr] = pk(bv, bv);
        }
        __syncthreads();
        #pragma unroll
        for (int kk = 0; kk < 16; kk++) {
            ull a01 = *(const ull*)&As[kk][ty * 4];
            ull a23 = *(const ull*)&As[kk][ty * 4 + 2];
            #pragma unroll
            for (int j = 0; j < 4; j++) {
                ull b = Bs[kk][tx + 16 * j];
                acc[0][j] = f2fma(a01, b, acc[0][j]);
                acc[1][j] = f2fma(a23, b, acc[1][j]);
            }
        }
        __syncthreads();
    }
    #pragma unroll
    for (int j = 0; j < 4; j++) {
        int c = tx + 16 * j;
        if (c >= M1) continue;
        float bsv = bias1 ? bias1[c] : 0.0f;
        float v0, v1, v2, v3;
        upk(acc[0][j], v0, v1);
        upk(acc[1][j], v2, v3);
        int r = r0 + ty * 4;
        C1[(size_t)(r + 0) * M1 + c] = v0 + bsv;
        C1[(size_t)(r + 1) * M1 + c] = v1 + bsv;
        C1[(size_t)(r + 2) * M1 + c] = v2 + bsv;
        C1[(size_t)(r + 3) * M1 + c] = v3 + bsv;
    }
}

// ---------------- GAT: per-node attention logits (+ tick reset) --------------
__global__ void att_logits(const float* __restrict__ asrc, const float* __restrict__ adst) {
    int i = blockIdx.x * blockDim.x + threadIdx.x;
    if (i < 256) g_tick[i] = 0;
    if (i >= Nn * NHEADS) return;
    int n = i >> 2, hd = i & 3;
    const float4* xp = (const float4*)&g_xp[n * Hh + hd * DHd];
    const float4* as = (const float4*)&asrc[hd * DHd];
    const float4* ad = (const float4*)&adst[hd * DHd];
    float s = 0.0f, t = 0.0f;
    #pragma unroll
    for (int d4 = 0; d4 < 8; d4++) {
        float4 v = xp[d4], a = as[d4], b = ad[d4];
        s += v.x*a.x + v.y*a.y + v.z*a.z + v.w*a.w;
        t += v.x*b.x + v.y*b.y + v.z*b.z + v.w*b.w;
    }
    g_als[i] = s;
    g_ald[i] = t;
}

__device__ __forceinline__ float leaky(float x) { return x >= 0.0f ? x : 0.2f * x; }

struct FlashSmem {
    float Ks[64][36];
    float Vs[64][40];
    float Ps[4][16][68];
};

// ---------------- FAT kernel: blocks [0,1024) = flash, [1024,5120) = GAT -----
__global__ void __launch_bounds__(128) gat_flash(
        const float* __restrict__ bias, const float* __restrict__ g0,
        const float* __restrict__ b0) {
    __shared__ FlashSmem sm;
    __shared__ int s_last;
    const int t = threadIdx.x;
    const float NEGINF = -__int_as_float(0x7f800000);

    if (blockIdx.x < FLASHBLK) {
        const int fb = blockIdx.x;
        const int qt = fb & 63;
        const int hd = (fb >> 6) & 3;
        const int sp = fb >> 8;
        const int w = t >> 5, lane = t & 31;
        const int gi = lane >> 2, li = lane & 3;
        const int q0 = qt * 64 + w * 16;
        const int kbase = sp * (Nn / KSPLIT);

        unsigned qa[4][4];
        {
            // 1/sqrt(32) * log2(e): scores land in log2 domain
            const float scq = 0.17677669529663687f * 1.4426950408889634f;
            #pragma unroll
            for (int ks = 0; ks < 4; ks++) {
                int c = hd * 32 + ks * 8 + li;
                qa[ks][0] = tf32u(g_qkv[(q0+gi  )*384 + c] * scq);
                qa[ks][1] = tf32u(g_qkv[(q0+gi+8)*384 + c] * scq);
                qa[ks][2] = tf32u(g_qkv[(q0+gi  )*384 + c+4] * scq);
                qa[ks][3] = tf32u(g_qkv[(q0+gi+8)*384 + c+4] * scq);
            }
        }

        float4 kst[4], vst[4];
        auto ldg_tile = [&](int ti) {
            int kb = kbase + ti * 64;
            #pragma unroll
            for (int i = 0; i < 4; i++) {
                int c = t + i * 128;
                int j = c >> 3, d4 = c & 7;
                const float4* p = (const float4*)&g_qkv[(kb + j) * 384 + 128 + hd * 32 + d4 * 4];
                kst[i] = p[0];
                vst[i] = p[32];
            }
        };
        auto sts_tile = [&]() {
            #pragma unroll
            for (int i = 0; i < 4; i++) {
                int c = t + i * 128;
                int j = c >> 3, d4 = c & 7;
                float4 k4 = kst[i], v4 = vst[i];
                k4.x = tf32f(k4.x); k4.y = tf32f(k4.y); k4.z = tf32f(k4.z); k4.w = tf32f(k4.w);
                v4.x = tf32f(v4.x); v4.y = tf32f(v4.y); v4.z = tf32f(v4.z); v4.w = tf32f(v4.w);
                *(float4*)&sm.Ks[j][d4 * 4] = k4;
                *(float4*)&sm.Vs[j][d4 * 4] = v4;
            }
        };

        float mxl = NEGINF, mxh = NEGINF, lsl = 0.0f, lsh = 0.0f;
        float o[4][4];
        #pragma unroll
        for (int jn = 0; jn < 4; jn++)
            #pragma unroll
            for (int i = 0; i < 4; i++) o[jn][i] = 0.0f;

        ldg_tile(0);
        for (int ti = 0; ti < NTILES; ti++) {
            __syncthreads();
            sts_tile();
            if (ti + 1 < NTILES) ldg_tile(ti + 1);
            __syncthreads();

            float s[8][4];
            #pragma unroll
            for (int jk = 0; jk < 8; jk++) {
                s[jk][0] = s[jk][1] = s[jk][2] = s[jk][3] = 0.0f;
                #pragma unroll
                for (int ks = 0; ks < 4; ks++) {
                    unsigned b0v = __float_as_uint(sm.Ks[jk*8+gi][ks*8+li]);
                    unsigned b1v = __float_as_uint(sm.Ks[jk*8+gi][ks*8+li+4]);
                    mma_tf32(s[jk], qa[ks], b0v, b1v);
                }
            }
            float tml = NEGINF, tmh = NEGINF;
            #pragma unroll
            for (int jk = 0; jk < 8; jk++) {
                tml = fmaxf(tml, fmaxf(s[jk][0], s[jk][1]));
                tmh = fmaxf(tmh, fmaxf(s[jk][2], s[jk][3]));
            }
            tml = fmaxf(tml, __shfl_xor_sync(0xffffffffu, tml, 1));
            tml = fmaxf(tml, __shfl_xor_sync(0xffffffffu, tml, 2));
            tmh = fmaxf(tmh, __shfl_xor_sync(0xffffffffu, tmh, 1));
            tmh = fmaxf(tmh, __shfl_xor_sync(0xffffffffu, tmh, 2));
            float nml = fmaxf(mxl, tml), nmh = fmaxf(mxh, tmh);
            float scl = ex2(mxl - nml), sch = ex2(mxh - nmh);
            mxl = nml; mxh = nmh;
            lsl *= scl; lsh *= sch;
            #pragma unroll
            for (int jn = 0; jn < 4; jn++) {
                o[jn][0] *= scl; o[jn][1] *= scl;
                o[jn][2] *= sch; o[jn][3] *= sch;
            }
            float rsl = 0.0f, rsh = 0.0f;
            #pragma unroll
            for (int jk = 0; jk < 8; jk++) {
                float p0 = ex2(s[jk][0] - mxl), p1 = ex2(s[jk][1] - mxl);
                float p2 = ex2(s[jk][2] - mxh), p3 = ex2(s[jk][3] - mxh);
                rsl += p0 + p1; rsh += p2 + p3;
                float2 lo = make_float2(tf32f(p0), tf32f(p1));
                float2 hi = make_float2(tf32f(p2), tf32f(p3));
                *(float2*)&sm.Ps[w][gi  ][jk*8 + 2*li] = lo;
                *(float2*)&sm.Ps[w][gi+8][jk*8 + 2*li] = hi;
            }
            rsl += __shfl_xor_sync(0xffffffffu, rsl, 1);
            rsl += __shfl_xor_sync(0xffffffffu, rsl, 2);
            rsh += __shfl_xor_sync(0xffffffffu, rsh, 1);
            rsh += __shfl_xor_sync(0xffffffffu, rsh, 2);
            lsl += rsl; lsh += rsh;
            __syncwarp();
            #pragma unroll
            for (int kk = 0; kk < 8; kk++) {
                unsigned pa[4];
                pa[0] = __float_as_uint(sm.Ps[w][gi  ][kk*8 + li]);
                pa[1] = __float_as_uint(sm.Ps[w][gi+8][kk*8 + li]);
                pa[2] = __float_as_uint(sm.Ps[w][gi  ][kk*8 + li + 4]);
                pa[3] = __float_as_uint(sm.Ps[w][gi+8][kk*8 + li + 4]);
                #pragma unroll
                for (int jn = 0; jn < 4; jn++) {
                    unsigned b0v = __float_as_uint(sm.Vs[kk*8+li  ][jn*8+gi]);
                    unsigned b1v = __float_as_uint(sm.Vs[kk*8+li+4][jn*8+gi]);
                    mma_tf32(o[jn], pa, b0v, b1v);
                }
            }
            __syncwarp();
        }

        const int nl = q0 + gi, nh = nl + 8;
        const int qhl = nl * 4 + hd, qhh = nh * 4 + hd;
        if (li == 0) {
            g_pm[sp * NQH + qhl] = mxl;    // log2 domain
            g_pl[sp * NQH + qhl] = lsl;
            g_pm[sp * NQH + qhh] = mxh;
            g_pl[sp * NQH + qhh] = lsh;
        }
        #pragma unroll
        for (int jn = 0; jn < 4; jn++) {
            int dh = jn * 8 + 2 * li;
            *(float2*)&g_pacc[((size_t)sp * NQH + qhl) * DHd + dh] = make_float2(o[jn][0], o[jn][1]);
            *(float2*)&g_pacc[((size_t)sp * NQH + qhh) * DHd + dh] = make_float2(o[jn][2], o[jn][3]);
        }

        // ---- fused split-K merge (log2-domain weights) ----
        __threadfence();
        if (t == 0) {
            int v = atomicAdd(&g_tick[(qt << 2) | hd], 1);
            s_last = (v == KSPLIT - 1);
        }
        __syncthreads();
        if (s_last) {
            for (int i = t; i < 64 * DHd; i += 128) {
                int q = i >> 5, dd = i & 31;
                int n = qt * 64 + q;
                int qh = n * 4 + hd;
                float m0 = g_pm[0*NQH+qh], m1 = g_pm[1*NQH+qh];
                float m2 = g_pm[2*NQH+qh], m3 = g_pm[3*NQH+qh];
                float M = fmaxf(fmaxf(m0, m1), fmaxf(m2, m3));
                float w0 = ex2(m0 - M), w1 = ex2(m1 - M);
                float w2 = ex2(m2 - M), w3 = ex2(m3 - M);
                float L = g_pl[0*NQH+qh]*w0 + g_pl[1*NQH+qh]*w1
                        + g_pl[2*NQH+qh]*w2 + g_pl[3*NQH+qh]*w3;
                float a = g_pacc[((size_t)0*NQH+qh)*DHd + dd] * w0
                        + g_pacc[((size_t)1*NQH+qh)*DHd + dd] * w1
                        + g_pacc[((size_t)2*NQH+qh)*DHd + dd] * w2
                        + g_pacc[((size_t)3*NQH+qh)*DHd + dd] * w3;
                g_attn[n * Hh + hd * DHd + dd] = a / L;
            }
        }
    } else {
        // =========== GAT aggregation: warp w = head w, lane = channel ===========
        const int d = blockIdx.x - FLASHBLK;
        const int w = t >> 5, lane = t & 31;
        const int beg = g_rowptr[d], end = g_rowptr[d + 1];
        const float adh = g_ald[d * 4 + w];

        float mx = NEGINF;
        for (int e = beg + lane; e < end; e += 32) {
            int s = g_srcs[e];
            mx = fmaxf(mx, leaky(g_als[s * 4 + w] + adh));
        }
        #pragma unroll
        for (int off = 16; off > 0; off >>= 1)
            mx = fmaxf(mx, __shfl_xor_sync(0xffffffffu, mx, off));

        float den = 0.0f;
        float acc = 0.0f;
        const int c = w * 32 + lane;
        for (int cb = beg; cb < end; cb += 32) {
            int cnt = min(32, end - cb);
            int e = cb + lane;
            float wgt = 0.0f;
            int ssrc = 0;
            if (lane < cnt) {
                ssrc = g_srcs[e];
                wgt = __expf(leaky(g_als[ssrc * 4 + w] + adh) - mx);
            }
            den += wgt;
            for (int j = 0; j < cnt; j++) {
                float wj = __shfl_sync(0xffffffffu, wgt, j);
                int sj   = __shfl_sync(0xffffffffu, ssrc, j);
                acc = fmaf(wj, g_xp[sj * Hh + c], acc);
            }
        }
        #pragma unroll
        for (int off = 16; off > 0; off >>= 1)
            den += __shfl_xor_sync(0xffffffffu, den, off);

        float v = acc / (den + 1e-16f) + bias[c] + g_h[d * Hh + c];
        g_hloc[d * Hh + c] = v * bn_scale(g0[c]) + b0[c];
    }
}

// ---------------- host launch ----------------
extern "C" void kernel_launch(void* const* d_in, const int* in_sizes, int n_in,
                              void* d_out, int out_size) {
    const float* x       = (const float*)d_in[0];
    const int*   ei      = (const int*)d_in[1];
    const float* w_in    = (const float*)d_in[2];
    const float* b_in    = (const float*)d_in[3];
    const float* w_gat   = (const float*)d_in[4];
    const float* att_src = (const float*)d_in[5];
    const float* att_dst = (const float*)d_in[6];
    const float* b_gat   = (const float*)d_in[7];
    const float* w_qkv   = (const float*)d_in[8];
    const float* b_qkv   = (const float*)d_in[9];
    const float* w_o     = (const float*)d_in[10];
    const float* b_o     = (const float*)d_in[11];
    const float* bn_g    = (const float*)d_in[12];
    const float* bn_b    = (const float*)d_in[13];
    const float* w1      = (const float*)d_in[14];
    const float* b1      = (const float*)d_in[15];
    const float* w2      = (const float*)d_in[16];
    const float* b2      = (const float*)d_in[17];
    const float* w_out   = (const float*)d_in[18];
    const float* b_out   = (const float*)d_in[19];
    float* out = (float*)d_out;

    float *p_h, *p_xp, *p_qkv, *p_attn, *p_out, *p_t1, *p_hloc;
    int* p_cnt;
    cudaGetSymbolAddress((void**)&p_h,    g_h);
    cudaGetSymbolAddress((void**)&p_xp,   g_xp);
    cudaGetSymbolAddress((void**)&p_qkv,  g_qkv);
    cudaGetSymbolAddress((void**)&p_attn, g_attn);
    cudaGetSymbolAddress((void**)&p_out,  g_out);
    cudaGetSymbolAddress((void**)&p_t1,   g_t1);
    cudaGetSymbolAddress((void**)&p_hloc, g_hloc);
    cudaGetSymbolAddress((void**)&p_cnt,  g_cnt);

    // CSR count + input projection overlapped
    cudaMemsetAsync(p_cnt, 0, Nn * sizeof(int));
    fused_ingemm_hist<<<128 + Ee / 4096, 256>>>(ei, x, w_in, b_in, p_h);
    csr_scan<<<1, 1024>>>();

    for (int l = 0; l < Ll; l++) {
        if (l == 0) {
            // layer-0 GAT+QKV projection overlapped with CSR scatter
            fused_qkvgemm_scatter<<<512 + Ee / 256, 256>>>(
                ei, p_h, w_gat, w_qkv, b_qkv, p_xp, p_qkv);
        } else {
            gemm_tf32<<<dim3(8, 64), 256>>>(p_h,
                                            w_gat + l * Hh * Hh, nullptr, p_xp, Hh,
                                            w_qkv + l * 3 * Hh * Hh, b_qkv + l * 3 * Hh,
                                            p_qkv, 3 * Hh,
                                            Hh, 0, nullptr, nullptr, nullptr, nullptr);
        }
        att_logits<<<(Nn * NHEADS + 127) / 128, 128>>>(att_src + l * Hh, att_dst + l * Hh);

        // FAT kernel: flash attention (split-K merge fused) + GAT aggregation
        gat_flash<<<FLASHBLK + Nn, 128>>>(b_gat + l * Hh,
                                          bn_g + (l * 3 + 0) * Hh, bn_b + (l * 3 + 0) * Hh);

        // w_o GEMM with fused combine_att epilogue -> g_out
        gemm_tf32<<<dim3(2, 64), 256>>>(p_attn, w_o + l * Hh * Hh, b_o + l * Hh, p_out, Hh,
                                        nullptr, nullptr, nullptr, 0, Hh, 2,
                                        p_hloc, p_h,
                                        bn_g + (l * 3 + 1) * Hh, bn_b + (l * 3 + 1) * Hh);

        // MLP
        gemm_tf32<<<dim3(4, 64), 256>>>(p_out, w1 + l * 2 * Hh * Hh, b1 + l * 2 * Hh, p_t1, 2 * Hh,
                                        nullptr, nullptr, nullptr, 0, Hh, 1,
                                        nullptr, nullptr, nullptr, nullptr);
        // w2 GEMM with fused final_combine epilogue -> g_h
        gemm_tf32<<<dim3(2, 64), 256>>>(p_t1, w2 + l * 2 * Hh * Hh, b2 + l * Hh, p_h, Hh,
                                        nullptr, nullptr, nullptr, 0, 2 * Hh, 3,
                                        p_out, p_h,
                                        bn_g + (l * 3 + 2) * Hh, bn_b + (l * 3 + 2) * Hh);
    }

    // output projection -> [4096, 2] (scalar path, M=2)
    gemm_nt<<<dim3(1, 64), dim3(16, 16)>>>(p_h, w_out, b_out, out, 2, Nn, Hh);
}

// round 11
// speedup vs baseline: 1.0801x; 1.0233x over previous
#include <cuda_runtime.h>
#include <math.h>

#define Nn 4096
#define Ee 262144
#define IND 64
#define Hh 128
#define NHEADS 4
#define DHd 32
#define Ll 2
#define KSPLIT 4
#define NQH (Nn * NHEADS)
#define FLASHBLK ((Nn / 64) * NHEADS * KSPLIT)   // 1024
#define NTILES ((Nn / KSPLIT) / 64)              // 16

typedef unsigned long long ull;

// ---------------- scratch (static device globals; no allocation) -------------
__device__ float g_h[Nn*Hh];
__device__ float g_xp[Nn*Hh];
__device__ float g_alsd[Nn*8];          // [n][0..3]=als heads, [4..7]=ald heads
__device__ float g_asv[Ll*2*NHEADS*Hh]; // [l][src/dst][h][c]
__device__ float g_hloc[Nn*Hh];
__device__ float g_qkv[Nn*3*Hh];
__device__ float g_attn[Nn*Hh];
__device__ float g_out[Nn*Hh];
__device__ float g_t1[Nn*2*Hh];
// flash split-K partials
__device__ float g_pm[KSPLIT*NQH];
__device__ float g_pl[KSPLIT*NQH];
__device__ float g_pacc[KSPLIT*NQH*DHd];
__device__ int   g_tick[256];           // zero-init; self-resetting
// CSR
__device__ int g_cnt[Nn];
__device__ int g_cursor[Nn];
__device__ int g_rowptr[Nn+1];
__device__ int g_srcs[Ee];

__device__ __forceinline__ float bn_scale(float g) { return g * rsqrtf(1.0f + 1e-5f); }

__device__ __forceinline__ float ex2(float x) {
    float r; asm("ex2.approx.f32 %0,%1;" : "=f"(r) : "f"(x)); return r;
}
__device__ __forceinline__ void cpa16(void* sdst, const void* gsrc) {
    unsigned s = (unsigned)__cvta_generic_to_shared(sdst);
    asm volatile("cp.async.cg.shared.global [%0],[%1],16;" :: "r"(s), "l"(gsrc));
}

// ---- tf32 helpers ----
__device__ __forceinline__ unsigned tf32u(float f) {
    unsigned r; asm("cvt.rna.tf32.f32 %0,%1;" : "=r"(r) : "f"(f)); return r;
}
__device__ __forceinline__ float tf32f(float f) {
    return __uint_as_float(tf32u(f));
}
__device__ __forceinline__ void mma_tf32(float* d, const unsigned* a, unsigned b0, unsigned b1) {
    asm volatile(
        "mma.sync.aligned.m16n8k8.row.col.f32.tf32.tf32.f32 "
        "{%0,%1,%2,%3},{%4,%5,%6,%7},{%8,%9},{%0,%1,%2,%3};"
        : "+f"(d[0]), "+f"(d[1]), "+f"(d[2]), "+f"(d[3])
        : "r"(a[0]), "r"(a[1]), "r"(a[2]), "r"(a[3]), "r"(b0), "r"(b1));
}

// ---------------- tf32 GEMM core (64x64 tile, cp.async double-buffered) ------
// mode 0: none  1: relu
// mode 2: C1 = epA + (acc+bias + epH) * bn_scale(epG) + epB
// mode 3: C1 = max((epA + acc+bias) * bn_scale(epG) + epB + epH, 0)
__device__ __forceinline__ void gemm_core(
        float (*As)[64][36], float (*Bs)[64][36], int bx, int by,
        const float* __restrict__ A,
        const float* __restrict__ B1, const float* __restrict__ bias1,
        float* __restrict__ C1, int M1,
        const float* __restrict__ B2, const float* __restrict__ bias2,
        float* __restrict__ C2, int M2,
        int K, int mode,
        const float* __restrict__ epA, const float* __restrict__ epH,
        const float* __restrict__ epG, const float* __restrict__ epB) {
    const int t = threadIdx.x;
    const int w = t >> 5, lane = t & 31;
    const int gi = lane >> 2, li = lane & 3;
    const int wr = w >> 2, wc = w & 3;
    const int r0 = by * 64;
    const int c0 = bx * 64;
    const int row_s = t >> 3;
    const int kq4 = (t & 7) * 4;

    float o[2][2][4];
    #pragma unroll
    for (int mt = 0; mt < 2; mt++)
        #pragma unroll
        for (int nt = 0; nt < 2; nt++)
            #pragma unroll
            for (int i = 0; i < 4; i++) o[mt][nt][i] = 0.0f;

    auto stage = [&](int kc, int buf) {
        #pragma unroll
        for (int i = 0; i < 2; i++) {
            int row = row_s + i * 32;
            cpa16(&As[buf][row][kq4], &A[(size_t)(r0 + row) * K + kc + kq4]);
            int cc = c0 + row;
            const float* Brow = (cc < M1) ? (B1 + (size_t)cc * K)
                                          : (B2 + (size_t)(cc - M1) * K);
            cpa16(&Bs[buf][row][kq4], &Brow[kc + kq4]);
        }
        asm volatile("cp.async.commit_group;");
    };

    const int nc = K >> 5;
    stage(0, 0);
    for (int ci = 0; ci < nc; ci++) {
        int buf = ci & 1;
        if (ci + 1 < nc) {
            stage((ci + 1) << 5, buf ^ 1);
            asm volatile("cp.async.wait_group 1;");
        } else {
            asm volatile("cp.async.wait_group 0;");
        }
        __syncthreads();
        #pragma unroll
        for (int k8 = 0; k8 < 32; k8 += 8) {
            unsigned a[2][4];
            #pragma unroll
            for (int mt = 0; mt < 2; mt++) {
                int row = wr * 32 + mt * 16;
                a[mt][0] = tf32u(As[buf][row + gi    ][k8 + li]);
                a[mt][1] = tf32u(As[buf][row + gi + 8][k8 + li]);
                a[mt][2] = tf32u(As[buf][row + gi    ][k8 + li + 4]);
                a[mt][3] = tf32u(As[buf][row + gi + 8][k8 + li + 4]);
            }
            unsigned b[2][2];
            #pragma unroll
            for (int nt = 0; nt < 2; nt++) {
                int col = wc * 16 + nt * 8;
                b[nt][0] = tf32u(Bs[buf][col + gi][k8 + li]);
                b[nt][1] = tf32u(Bs[buf][col + gi][k8 + li + 4]);
            }
            #pragma unroll
            for (int mt = 0; mt < 2; mt++)
                #pragma unroll
                for (int nt = 0; nt < 2; nt++)
                    mma_tf32(o[mt][nt], a[mt], b[nt][0], b[nt][1]);
        }
        __syncthreads();
    }

    #pragma unroll
    for (int nt = 0; nt < 2; nt++) {
        int c = c0 + wc * 16 + nt * 8 + 2 * li;
        const float* bias; float* Cp; int ld, cc;
        if (c < M1) { bias = bias1; Cp = C1; ld = M1; cc = c; }
        else        { bias = bias2; Cp = C2; ld = M2; cc = c - M1; }
        float b0v = bias ? bias[cc] : 0.0f;
        float b1v = bias ? bias[cc + 1] : 0.0f;
        float gs0 = 0.f, gs1 = 0.f, gb0 = 0.f, gb1 = 0.f;
        if (mode >= 2) {
            gs0 = bn_scale(epG[c]); gs1 = bn_scale(epG[c + 1]);
            gb0 = epB[c]; gb1 = epB[c + 1];
        }
        #pragma unroll
        for (int mt = 0; mt < 2; mt++) {
            #pragma unroll
            for (int half = 0; half < 2; half++) {
                int r = r0 + wr * 32 + mt * 16 + gi + half * 8;
                float v0 = o[mt][nt][half * 2]     + b0v;
                float v1 = o[mt][nt][half * 2 + 1] + b1v;
                if (mode == 1) { v0 = fmaxf(v0, 0.f); v1 = fmaxf(v1, 0.f); }
                else if (mode == 2) {
                    float2 ea = *(const float2*)&epA[(size_t)r * ld + cc];
                    float2 eh = *(const float2*)&epH[(size_t)r * ld + cc];
                    v0 = ea.x + (v0 + eh.x) * gs0 + gb0;
                    v1 = ea.y + (v1 + eh.y) * gs1 + gb1;
                } else if (mode == 3) {
                    float2 ea = *(const float2*)&epA[(size_t)r * ld + cc];
                    float2 eh = *(const float2*)&epH[(size_t)r * ld + cc];
                    v0 = fmaxf((ea.x + v0) * gs0 + gb0 + eh.x, 0.f);
                    v1 = fmaxf((ea.y + v1) * gs1 + gb1 + eh.y, 0.f);
                }
                *(float2*)&Cp[(size_t)r * ld + cc] = make_float2(v0, v1);
            }
        }
    }
}

// standalone tf32 GEMM
__global__ void __launch_bounds__(256) gemm_tf32(
        const float* __restrict__ A,
        const float* __restrict__ B1, const float* __restrict__ bias1,
        float* __restrict__ C1, int M1,
        const float* __restrict__ B2, const float* __restrict__ bias2,
        float* __restrict__ C2, int M2,
        int K, int mode,
        const float* __restrict__ epA, const float* __restrict__ epH,
        const float* __restrict__ epG, const float* __restrict__ epB) {
    __shared__ float As[2][64][36];
    __shared__ float Bs[2][64][36];
    gemm_core(As, Bs, blockIdx.x, blockIdx.y, A, B1, bias1, C1, M1,
              B2, bias2, C2, M2, K, mode, epA, epH, epG, epB);
}

// fused: [0,128) input GEMM, [128,192) CSR hist, [192,200) asv precompute
__global__ void __launch_bounds__(256) fused_ingemm_hist(
        const int* __restrict__ ei,
        const float* __restrict__ x,
        const float* __restrict__ w_in, const float* __restrict__ b_in,
        float* __restrict__ C,
        const float* __restrict__ w_gat,
        const float* __restrict__ att_src, const float* __restrict__ att_dst) {
    __shared__ __align__(16) char smbuf[2 * 64 * 36 * 4 * 2];
    const int t = threadIdx.x;
    if (blockIdx.x < 128) {
        float (*As)[64][36] = (float(*)[64][36])smbuf;
        float (*Bs)[64][36] = (float(*)[64][36])(smbuf + 2 * 64 * 36 * 4);
        gemm_core(As, Bs, blockIdx.x & 1, blockIdx.x >> 1, x, w_in, b_in, C, Hh,
                  nullptr, nullptr, nullptr, 0, IND, 1,
                  nullptr, nullptr, nullptr, nullptr);
    } else if (blockIdx.x < 192) {
        int* hist = (int*)smbuf;
        for (int i = t; i < Nn; i += 256) hist[i] = 0;
        __syncthreads();
        const int base = (blockIdx.x - 128) * 4096;
        #pragma unroll 4
        for (int i = t; i < 4096; i += 256)
            atomicAdd(&hist[ei[Ee + base + i]], 1);
        __syncthreads();
        for (int i = t; i < Nn; i += 256) {
            int v = hist[i];
            if (v) atomicAdd(&g_cnt[i], v);
        }
    } else {
        // asv[l][sd][h][c] = sum_d a[l][h][d] * w_gat[l][(h*32+d)][c]
        int i = (blockIdx.x - 192) * 256 + t;          // 0..2047
        int c  = i & 127;
        int h  = (i >> 7) & 3;
        int sd = (i >> 9) & 1;
        int l  = i >> 10;
        const float* av = (sd == 0 ? att_src : att_dst) + l * Hh + h * DHd;
        const float* wg = w_gat + (size_t)l * Hh * Hh + (size_t)(h * DHd) * Hh + c;
        float s = 0.0f;
        #pragma unroll
        for (int d = 0; d < DHd; d++)
            s = fmaf(av[d], wg[(size_t)d * Hh], s);
        g_asv[i] = s;
    }
}

// fused per-layer projection:
//  [0,512): GAT+QKV GEMM   [512,640): alsd mat-vec   [640,640+Ee/256): scatter (l==0)
__global__ void __launch_bounds__(256) fused_proj(
        const int* __restrict__ ei, int do_scatter, int layer,
        const float* __restrict__ A,
        const float* __restrict__ w_gat,
        const float* __restrict__ w_qkv, const float* __restrict__ b_qkv,
        float* __restrict__ Cxp, float* __restrict__ Cqkv) {
    __shared__ float As[2][64][36];
    __shared__ float Bs[2][64][36];
    if (blockIdx.x < 512) {
        gemm_core(As, Bs, blockIdx.x & 7, blockIdx.x >> 3, A,
                  w_gat, nullptr, Cxp, Hh,
                  w_qkv, b_qkv, Cqkv, 3 * Hh,
                  Hh, 0, nullptr, nullptr, nullptr, nullptr);
    } else if (blockIdx.x < 640) {
        // alsd: thread -> (n, j): j = sd*4+h; dot(h[n,:], asv[layer][sd][h][:])
        int i = (blockIdx.x - 512) * 256 + threadIdx.x;   // 0..32767
        int j = i & 7;
        int n = i >> 3;
        const float4* hr = (const float4*)&A[(size_t)n * Hh];
        int sd = j >> 2, h = j & 3;
        const float4* av = (const float4*)&g_asv[((layer * 2 + sd) * NHEADS + h) * Hh];
        float s = 0.0f;
        #pragma unroll
        for (int q = 0; q < 32; q++) {
            float4 a = hr[q], b = av[q];
            s += a.x*b.x + a.y*b.y + a.z*b.z + a.w*b.w;
        }
        g_alsd[n * 8 + j] = s;
    } else if (do_scatter) {
        int e = (blockIdx.x - 640) * 256 + threadIdx.x;
        if (e < Ee) {
            int d = ei[Ee + e];
            int pos = atomicAdd(&g_cursor[d], 1);
            g_srcs[pos] = ei[e];
        }
    }
}

__global__ void csr_scan() {
    __shared__ int sm[1024];
    int t = threadIdx.x;
    int b = t * 4;
    int c0 = g_cnt[b], c1 = g_cnt[b+1], c2 = g_cnt[b+2], c3 = g_cnt[b+3];
    int s1 = c0 + c1, s2 = s1 + c2, s3 = s2 + c3;
    sm[t] = s3;
    __syncthreads();
    for (int off = 1; off < 1024; off <<= 1) {
        int v = (t >= off) ? sm[t - off] : 0;
        __syncthreads();
        sm[t] += v;
        __syncthreads();
    }
    int excl = sm[t] - s3;
    g_rowptr[b]   = excl;
    g_rowptr[b+1] = excl + c0;
    g_rowptr[b+2] = excl + s1;
    g_rowptr[b+3] = excl + s2;
    g_cursor[b]   = excl;
    g_cursor[b+1] = excl + c0;
    g_cursor[b+2] = excl + s1;
    g_cursor[b+3] = excl + s2;
    if (t == 1023) g_rowptr[Nn] = sm[1023];
}

// ---------------- output projection: warp per node, M=2 ----------------------
__global__ void __launch_bounds__(256) out_proj(
        const float* __restrict__ hsrc, const float* __restrict__ w_out,
        const float* __restrict__ b_out, float* __restrict__ out) {
    const int warp = threadIdx.x >> 5, lane = threadIdx.x & 31;
    const int n = blockIdx.x * 8 + warp;
    float4 h4 = *(const float4*)&hsrc[(size_t)n * Hh + lane * 4];
    float4 w0 = *(const float4*)&w_out[lane * 4];
    float4 w1 = *(const float4*)&w_out[Hh + lane * 4];
    float s0 = h4.x*w0.x + h4.y*w0.y + h4.z*w0.z + h4.w*w0.w;
    float s1 = h4.x*w1.x + h4.y*w1.y + h4.z*w1.z + h4.w*w1.w;
    #pragma unroll
    for (int off = 16; off > 0; off >>= 1) {
        s0 += __shfl_xor_sync(0xffffffffu, s0, off);
        s1 += __shfl_xor_sync(0xffffffffu, s1, off);
    }
    if (lane == 0) {
        out[n * 2]     = s0 + b_out[0];
        out[n * 2 + 1] = s1 + b_out[1];
    }
}

__device__ __forceinline__ float leaky(float x) { return x >= 0.0f ? x : 0.2f * x; }

struct FlashSmem {
    float Ks[64][36];
    float Vs[64][40];
    float Ps[4][16][68];   // 64 cols + 4 pad — P is 16x64 per warp (do NOT shrink)
};

// ---------------- FAT kernel: blocks [0,1024) = flash, [1024,5120) = GAT -----
__global__ void __launch_bounds__(128) gat_flash(
        const float* __restrict__ bias, const float* __restrict__ g0,
        const float* __restrict__ b0) {
    __shared__ FlashSmem sm;
    __shared__ int s_last;
    const int t = threadIdx.x;
    const float NEGINF = -__int_as_float(0x7f800000);

    if (blockIdx.x < FLASHBLK) {
        const int fb = blockIdx.x;
        const int qt = fb & 63;
        const int hd = (fb >> 6) & 3;
        const int sp = fb >> 8;
        const int w = t >> 5, lane = t & 31;
        const int gi = lane >> 2, li = lane & 3;
        const int q0 = qt * 64 + w * 16;
        const int kbase = sp * (Nn / KSPLIT);

        unsigned qa[4][4];
        {
            // 1/sqrt(32) * log2(e): scores land in log2 domain
            const float scq = 0.17677669529663687f * 1.4426950408889634f;
            #pragma unroll
            for (int ks = 0; ks < 4; ks++) {
                int c = hd * 32 + ks * 8 + li;
                qa[ks][0] = tf32u(g_qkv[(q0+gi  )*384 + c] * scq);
                qa[ks][1] = tf32u(g_qkv[(q0+gi+8)*384 + c] * scq);
                qa[ks][2] = tf32u(g_qkv[(q0+gi  )*384 + c+4] * scq);
                qa[ks][3] = tf32u(g_qkv[(q0+gi+8)*384 + c+4] * scq);
            }
        }

        float4 kst[4], vst[4];
        auto ldg_tile = [&](int ti) {
            int kb = kbase + ti * 64;
            #pragma unroll
            for (int i = 0; i < 4; i++) {
                int c = t + i * 128;
                int j = c >> 3, d4 = c & 7;
                const float4* p = (const float4*)&g_qkv[(kb + j) * 384 + 128 + hd * 32 + d4 * 4];
                kst[i] = p[0];
                vst[i] = p[32];
            }
        };
        auto sts_tile = [&]() {
            #pragma unroll
            for (int i = 0; i < 4; i++) {
                int c = t + i * 128;
                int j = c >> 3, d4 = c & 7;
                float4 k4 = kst[i], v4 = vst[i];
                k4.x = tf32f(k4.x); k4.y = tf32f(k4.y); k4.z = tf32f(k4.z); k4.w = tf32f(k4.w);
                v4.x = tf32f(v4.x); v4.y = tf32f(v4.y); v4.z = tf32f(v4.z); v4.w = tf32f(v4.w);
                *(float4*)&sm.Ks[j][d4 * 4] = k4;
                *(float4*)&sm.Vs[j][d4 * 4] = v4;
            }
        };

        float mxl = NEGINF, mxh = NEGINF, lsl = 0.0f, lsh = 0.0f;
        float o[4][4];
        #pragma unroll
        for (int jn = 0; jn < 4; jn++)
            #pragma unroll
            for (int i = 0; i < 4; i++) o[jn][i] = 0.0f;

        ldg_tile(0);
        for (int ti = 0; ti < NTILES; ti++) {
            __syncthreads();
            sts_tile();
            if (ti + 1 < NTILES) ldg_tile(ti + 1);
            __syncthreads();

            float s[8][4];
            #pragma unroll
            for (int jk = 0; jk < 8; jk++) {
                s[jk][0] = s[jk][1] = s[jk][2] = s[jk][3] = 0.0f;
                #pragma unroll
                for (int ks = 0; ks < 4; ks++) {
                    unsigned b0v = __float_as_uint(sm.Ks[jk*8+gi][ks*8+li]);
                    unsigned b1v = __float_as_uint(sm.Ks[jk*8+gi][ks*8+li+4]);
                    mma_tf32(s[jk], qa[ks], b0v, b1v);
                }
            }
            float tml = NEGINF, tmh = NEGINF;
            #pragma unroll
            for (int jk = 0; jk < 8; jk++) {
                tml = fmaxf(tml, fmaxf(s[jk][0], s[jk][1]));
                tmh = fmaxf(tmh, fmaxf(s[jk][2], s[jk][3]));
            }
            tml = fmaxf(tml, __shfl_xor_sync(0xffffffffu, tml, 1));
            tml = fmaxf(tml, __shfl_xor_sync(0xffffffffu, tml, 2));
            tmh = fmaxf(tmh, __shfl_xor_sync(0xffffffffu, tmh, 1));
            tmh = fmaxf(tmh, __shfl_xor_sync(0xffffffffu, tmh, 2));
            float nml = fmaxf(mxl, tml), nmh = fmaxf(mxh, tmh);
            float scl = ex2(mxl - nml), sch = ex2(mxh - nmh);
            mxl = nml; mxh = nmh;
            lsl *= scl; lsh *= sch;
            #pragma unroll
            for (int jn = 0; jn < 4; jn++) {
                o[jn][0] *= scl; o[jn][1] *= scl;
                o[jn][2] *= sch; o[jn][3] *= sch;
            }
            float rsl = 0.0f, rsh = 0.0f;
            #pragma unroll
            for (int jk = 0; jk < 8; jk++) {
                float p0 = ex2(s[jk][0] - mxl), p1 = ex2(s[jk][1] - mxl);
                float p2 = ex2(s[jk][2] - mxh), p3 = ex2(s[jk][3] - mxh);
                rsl += p0 + p1; rsh += p2 + p3;
                float2 lo = make_float2(tf32f(p0), tf32f(p1));
                float2 hi = make_float2(tf32f(p2), tf32f(p3));
                *(float2*)&sm.Ps[w][gi  ][jk*8 + 2*li] = lo;
                *(float2*)&sm.Ps[w][gi+8][jk*8 + 2*li] = hi;
            }
            rsl += __shfl_xor_sync(0xffffffffu, rsl, 1);
            rsl += __shfl_xor_sync(0xffffffffu, rsl, 2);
            rsh += __shfl_xor_sync(0xffffffffu, rsh, 1);
            rsh += __shfl_xor_sync(0xffffffffu, rsh, 2);
            lsl += rsl; lsh += rsh;
            __syncwarp();
            #pragma unroll
            for (int kk = 0; kk < 8; kk++) {
                unsigned pa[4];
                pa[0] = __float_as_uint(sm.Ps[w][gi  ][kk*8 + li]);
                pa[1] = __float_as_uint(sm.Ps[w][gi+8][kk*8 + li]);
                pa[2] = __float_as_uint(sm.Ps[w][gi  ][kk*8 + li + 4]);
                pa[3] = __float_as_uint(sm.Ps[w][gi+8][kk*8 + li + 4]);
                #pragma unroll
                for (int jn = 0; jn < 4; jn++) {
                    unsigned b0v = __float_as_uint(sm.Vs[kk*8+li  ][jn*8+gi]);
                    unsigned b1v = __float_as_uint(sm.Vs[kk*8+li+4][jn*8+gi]);
                    mma_tf32(o[jn], pa, b0v, b1v);
                }
            }
            __syncwarp();
        }

        const int nl = q0 + gi, nh = nl + 8;
        const int qhl = nl * 4 + hd, qhh = nh * 4 + hd;
        if (li == 0) {
            g_pm[sp * NQH + qhl] = mxl;    // log2 domain
            g_pl[sp * NQH + qhl] = lsl;
            g_pm[sp * NQH + qhh] = mxh;
            g_pl[sp * NQH + qhh] = lsh;
        }
        #pragma unroll
        for (int jn = 0; jn < 4; jn++) {
            int dh = jn * 8 + 2 * li;
            *(float2*)&g_pacc[((size_t)sp * NQH + qhl) * DHd + dh] = make_float2(o[jn][0], o[jn][1]);
            *(float2*)&g_pacc[((size_t)sp * NQH + qhh) * DHd + dh] = make_float2(o[jn][2], o[jn][3]);
        }

        // ---- fused split-K merge (log2-domain weights); tick self-resets ----
        __threadfence();
        if (t == 0) {
            int v = atomicAdd(&g_tick[(qt << 2) | hd], 1);
            s_last = (v == KSPLIT - 1);
            if (s_last) g_tick[(qt << 2) | hd] = 0;
        }
        __syncthreads();
        if (s_last) {
            for (int i = t; i < 64 * DHd; i += 128) {
                int q = i >> 5, dd = i & 31;
                int n = qt * 64 + q;
                int qh = n * 4 + hd;
                float m0 = g_pm[0*NQH+qh], m1 = g_pm[1*NQH+qh];
                float m2 = g_pm[2*NQH+qh], m3 = g_pm[3*NQH+qh];
                float M = fmaxf(fmaxf(m0, m1), fmaxf(m2, m3));
                float w0 = ex2(m0 - M), w1 = ex2(m1 - M);
                float w2 = ex2(m2 - M), w3 = ex2(m3 - M);
                float L = g_pl[0*NQH+qh]*w0 + g_pl[1*NQH+qh]*w1
                        + g_pl[2*NQH+qh]*w2 + g_pl[3*NQH+qh]*w3;
                float a = g_pacc[((size_t)0*NQH+qh)*DHd + dd] * w0
                        + g_pacc[((size_t)1*NQH+qh)*DHd + dd] * w1
                        + g_pacc[((size_t)2*NQH+qh)*DHd + dd] * w2
                        + g_pacc[((size_t)3*NQH+qh)*DHd + dd] * w3;
                g_attn[n * Hh + hd * DHd + dd] = a / L;
            }
        }
    } else {
        // =========== GAT aggregation: warp w = head w, lane = channel ===========
        const int d = blockIdx.x - FLASHBLK;
        const int w = t >> 5, lane = t & 31;
        const int beg = g_rowptr[d], end = g_rowptr[d + 1];
        const float adh = g_alsd[d * 8 + 4 + w];

        float mx = NEGINF;
        for (int e = beg + lane; e < end; e += 32) {
            int s = g_srcs[e];
            mx = fmaxf(mx, leaky(g_alsd[s * 8 + w] + adh));
        }
        #pragma unroll
        for (int off = 16; off > 0; off >>= 1)
            mx = fmaxf(mx, __shfl_xor_sync(0xffffffffu, mx, off));

        float den = 0.0f;
        float acc = 0.0f;
        const int c = w * 32 + lane;
        for (int cb = beg; cb < end; cb += 32) {
            int cnt = min(32, end - cb);
            int e = cb + lane;
            float wgt = 0.0f;
            int ssrc = 0;
            if (lane < cnt) {
                ssrc = g_srcs[e];
                wgt = __expf(leaky(g_alsd[ssrc * 8 + w] + adh) - mx);
            }
            den += wgt;
            for (int j = 0; j < cnt; j++) {
                float wj = __shfl_sync(0xffffffffu, wgt, j);
                int sj   = __shfl_sync(0xffffffffu, ssrc, j);
                acc = fmaf(wj, g_xp[sj * Hh + c], acc);
            }
        }
        #pragma unroll
        for (int off = 16; off > 0; off >>= 1)
            den += __shfl_xor_sync(0xffffffffu, den, off);

        float v = acc / (den + 1e-16f) + bias[c] + g_h[d * Hh + c];
        g_hloc[d * Hh + c] = v * bn_scale(g0[c]) + b0[c];
    }
}

// ---------------- host launch ----------------
extern "C" void kernel_launch(void* const* d_in, const int* in_sizes, int n_in,
                              void* d_out, int out_size) {
    const float* x       = (const float*)d_in[0];
    const int*   ei      = (const int*)d_in[1];
    const float* w_in    = (const float*)d_in[2];
    const float* b_in    = (const float*)d_in[3];
    const float* w_gat   = (const float*)d_in[4];
    const float* att_src = (const float*)d_in[5];
    const float* att_dst = (const float*)d_in[6];
    const float* b_gat   = (const float*)d_in[7];
    const float* w_qkv   = (const float*)d_in[8];
    const float* b_qkv   = (const float*)d_in[9];
    const float* w_o     = (const float*)d_in[10];
    const float* b_o     = (const float*)d_in[11];
    const float* bn_g    = (const float*)d_in[12];
    const float* bn_b    = (const float*)d_in[13];
    const float* w1      = (const float*)d_in[14];
    const float* b1      = (const float*)d_in[15];
    const float* w2      = (const float*)d_in[16];
    const float* b2      = (const float*)d_in[17];
    const float* w_out   = (const float*)d_in[18];
    const float* b_out   = (const float*)d_in[19];
    float* out = (float*)d_out;

    float *p_h, *p_xp, *p_qkv, *p_attn, *p_out, *p_t1, *p_hloc;
    int* p_cnt;
    cudaGetSymbolAddress((void**)&p_h,    g_h);
    cudaGetSymbolAddress((void**)&p_xp,   g_xp);
    cudaGetSymbolAddress((void**)&p_qkv,  g_qkv);
    cudaGetSymbolAddress((void**)&p_attn, g_attn);
    cudaGetSymbolAddress((void**)&p_out,  g_out);
    cudaGetSymbolAddress((void**)&p_t1,   g_t1);
    cudaGetSymbolAddress((void**)&p_hloc, g_hloc);
    cudaGetSymbolAddress((void**)&p_cnt,  g_cnt);

    // CSR count + input projection + asv precompute overlapped
    cudaMemsetAsync(p_cnt, 0, Nn * sizeof(int));
    fused_ingemm_hist<<<200, 256>>>(ei, x, w_in, b_in, p_h, w_gat, att_src, att_dst);
    csr_scan<<<1, 1024>>>();

    for (int l = 0; l < Ll; l++) {
        // projection: GAT+QKV GEMM + alsd mat-vec (+ CSR scatter for l==0)
        int nblk = 640 + (l == 0 ? Ee / 256 : 0);
        fused_proj<<<nblk, 256>>>(ei, l == 0, l, p_h,
                                  w_gat + l * Hh * Hh,
                                  w_qkv + l * 3 * Hh * Hh, b_qkv + l * 3 * Hh,
                                  p_xp, p_qkv);

        // FAT kernel: flash attention (split-K merge fused) + GAT aggregation
        gat_flash<<<FLASHBLK + Nn, 128>>>(b_gat + l * Hh,
                                          bn_g + (l * 3 + 0) * Hh, bn_b + (l * 3 + 0) * Hh);

        // w_o GEMM with fused combine_att epilogue -> g_out
        gemm_tf32<<<dim3(2, 64), 256>>>(p_attn, w_o + l * Hh * Hh, b_o + l * Hh, p_out, Hh,
                                        nullptr, nullptr, nullptr, 0, Hh, 2,
                                        p_hloc, p_h,
                                        bn_g + (l * 3 + 1) * Hh, bn_b + (l * 3 + 1) * Hh);

        // MLP
        gemm_tf32<<<dim3(4, 64), 256>>>(p_out, w1 + l * 2 * Hh * Hh, b1 + l * 2 * Hh, p_t1, 2 * Hh,
                                        nullptr, nullptr, nullptr, 0, Hh, 1,
                                        nullptr, nullptr, nullptr, nullptr);
        // w2 GEMM with fused final_combine epilogue -> g_h
        gemm_tf32<<<dim3(2, 64), 256>>>(p_t1, w2 + l * 2 * Hh * Hh, b2 + l * Hh, p_h, Hh,
                                        nullptr, nullptr, nullptr, 0, 2 * Hh, 3,
                                        p_out, p_h,
                                        bn_g + (l * 3 + 2) * Hh, bn_b + (l * 3 + 2) * Hh);
    }

    // output projection -> [4096, 2]
    out_proj<<<Nn / 8, 256>>>(p_h, w_out, b_out, out);
}

// round 12
// speedup vs baseline: 1.1087x; 1.0265x over previous
#include <cuda_runtime.h>
#include <math.h>

#define Nn 4096
#define Ee 262144
#define IND 64
#define Hh 128
#define NHEADS 4
#define DHd 32
#define Ll 2
#define KSPLIT 4
#define NQH (Nn * NHEADS)
#define FLASHBLK ((Nn / 64) * NHEADS * KSPLIT)   // 1024
#define NTILES ((Nn / KSPLIT) / 64)              // 16

typedef unsigned long long ull;

// ---------------- scratch (static device globals; no allocation) -------------
__device__ float g_h[Nn*Hh];
__device__ float g_xp[Nn*Hh];
__device__ float g_alsd[Nn*8];          // [n][0..3]=als heads, [4..7]=ald heads
__device__ float g_asv[Ll*2*NHEADS*Hh]; // [l][src/dst][h][c]
__device__ float g_hloc[Nn*Hh];
__device__ float g_qkv[Nn*3*Hh];
__device__ float g_attn[Nn*Hh];
__device__ float g_out[Nn*Hh];
__device__ float g_t1[Nn*2*Hh];
// flash split-K partials
__device__ float g_pm[KSPLIT*NQH];
__device__ float g_pl[KSPLIT*NQH];
__device__ float g_pacc[KSPLIT*NQH*DHd];
__device__ int   g_tick[256];           // zero-init; self-resetting
// CSR
__device__ int g_cnt[Nn];
__device__ int g_cursor[Nn];
__device__ int g_rowptr[Nn+1];
__device__ int g_srcs[Ee];

__device__ __forceinline__ float bn_scale(float g) { return g * rsqrtf(1.0f + 1e-5f); }

__device__ __forceinline__ float ex2(float x) {
    float r; asm("ex2.approx.f32 %0,%1;" : "=f"(r) : "f"(x)); return r;
}
__device__ __forceinline__ void cpa16(void* sdst, const void* gsrc) {
    unsigned s = (unsigned)__cvta_generic_to_shared(sdst);
    asm volatile("cp.async.cg.shared.global [%0],[%1],16;" :: "r"(s), "l"(gsrc));
}

// ---- tf32 helpers ----
__device__ __forceinline__ unsigned tf32u(float f) {
    unsigned r; asm("cvt.rna.tf32.f32 %0,%1;" : "=r"(r) : "f"(f)); return r;
}
__device__ __forceinline__ float tf32f(float f) {
    return __uint_as_float(tf32u(f));
}
__device__ __forceinline__ void mma_tf32(float* d, const unsigned* a, unsigned b0, unsigned b1) {
    asm volatile(
        "mma.sync.aligned.m16n8k8.row.col.f32.tf32.tf32.f32 "
        "{%0,%1,%2,%3},{%4,%5,%6,%7},{%8,%9},{%0,%1,%2,%3};"
        : "+f"(d[0]), "+f"(d[1]), "+f"(d[2]), "+f"(d[3])
        : "r"(a[0]), "r"(a[1]), "r"(a[2]), "r"(a[3]), "r"(b0), "r"(b1));
}

// ---------------- tf32 GEMM core (64x64 tile, cp.async double-buffered) ------
// mode 0: none  1: relu
// mode 2: C1 = epA + (acc+bias + epH) * bn_scale(epG) + epB
// mode 3: C1 = max((epA + acc+bias) * bn_scale(epG) + epB + epH, 0)
__device__ __forceinline__ void gemm_core(
        float (*As)[64][36], float (*Bs)[64][36], int bx, int by,
        const float* __restrict__ A,
        const float* __restrict__ B1, const float* __restrict__ bias1,
        float* __restrict__ C1, int M1,
        const float* __restrict__ B2, const float* __restrict__ bias2,
        float* __restrict__ C2, int M2,
        int K, int mode,
        const float* __restrict__ epA, const float* __restrict__ epH,
        const float* __restrict__ epG, const float* __restrict__ epB) {
    const int t = threadIdx.x;
    const int w = t >> 5, lane = t & 31;
    const int gi = lane >> 2, li = lane & 3;
    const int wr = w >> 2, wc = w & 3;
    const int r0 = by * 64;
    const int c0 = bx * 64;
    const int row_s = t >> 3;
    const int kq4 = (t & 7) * 4;

    float o[2][2][4];
    #pragma unroll
    for (int mt = 0; mt < 2; mt++)
        #pragma unroll
        for (int nt = 0; nt < 2; nt++)
            #pragma unroll
            for (int i = 0; i < 4; i++) o[mt][nt][i] = 0.0f;

    auto stage = [&](int kc, int buf) {
        #pragma unroll
        for (int i = 0; i < 2; i++) {
            int row = row_s + i * 32;
            cpa16(&As[buf][row][kq4], &A[(size_t)(r0 + row) * K + kc + kq4]);
            int cc = c0 + row;
            const float* Brow = (cc < M1) ? (B1 + (size_t)cc * K)
                                          : (B2 + (size_t)(cc - M1) * K);
            cpa16(&Bs[buf][row][kq4], &Brow[kc + kq4]);
        }
        asm volatile("cp.async.commit_group;");
    };

    const int nc = K >> 5;
    stage(0, 0);
    for (int ci = 0; ci < nc; ci++) {
        int buf = ci & 1;
        if (ci + 1 < nc) {
            stage((ci + 1) << 5, buf ^ 1);
            asm volatile("cp.async.wait_group 1;");
        } else {
            asm volatile("cp.async.wait_group 0;");
        }
        __syncthreads();
        #pragma unroll
        for (int k8 = 0; k8 < 32; k8 += 8) {
            unsigned a[2][4];
            #pragma unroll
            for (int mt = 0; mt < 2; mt++) {
                int row = wr * 32 + mt * 16;
                a[mt][0] = tf32u(As[buf][row + gi    ][k8 + li]);
                a[mt][1] = tf32u(As[buf][row + gi + 8][k8 + li]);
                a[mt][2] = tf32u(As[buf][row + gi    ][k8 + li + 4]);
                a[mt][3] = tf32u(As[buf][row + gi + 8][k8 + li + 4]);
            }
            unsigned b[2][2];
            #pragma unroll
            for (int nt = 0; nt < 2; nt++) {
                int col = wc * 16 + nt * 8;
                b[nt][0] = tf32u(Bs[buf][col + gi][k8 + li]);
                b[nt][1] = tf32u(Bs[buf][col + gi][k8 + li + 4]);
            }
            #pragma unroll
            for (int mt = 0; mt < 2; mt++)
                #pragma unroll
                for (int nt = 0; nt < 2; nt++)
                    mma_tf32(o[mt][nt], a[mt], b[nt][0], b[nt][1]);
        }
        __syncthreads();
    }

    #pragma unroll
    for (int nt = 0; nt < 2; nt++) {
        int c = c0 + wc * 16 + nt * 8 + 2 * li;
        const float* bias; float* Cp; int ld, cc;
        if (c < M1) { bias = bias1; Cp = C1; ld = M1; cc = c; }
        else        { bias = bias2; Cp = C2; ld = M2; cc = c - M1; }
        float b0v = bias ? bias[cc] : 0.0f;
        float b1v = bias ? bias[cc + 1] : 0.0f;
        float gs0 = 0.f, gs1 = 0.f, gb0 = 0.f, gb1 = 0.f;
        if (mode >= 2) {
            gs0 = bn_scale(epG[c]); gs1 = bn_scale(epG[c + 1]);
            gb0 = epB[c]; gb1 = epB[c + 1];
        }
        #pragma unroll
        for (int mt = 0; mt < 2; mt++) {
            #pragma unroll
            for (int half = 0; half < 2; half++) {
                int r = r0 + wr * 32 + mt * 16 + gi + half * 8;
                float v0 = o[mt][nt][half * 2]     + b0v;
                float v1 = o[mt][nt][half * 2 + 1] + b1v;
                if (mode == 1) { v0 = fmaxf(v0, 0.f); v1 = fmaxf(v1, 0.f); }
                else if (mode == 2) {
                    float2 ea = *(const float2*)&epA[(size_t)r * ld + cc];
                    float2 eh = *(const float2*)&epH[(size_t)r * ld + cc];
                    v0 = ea.x + (v0 + eh.x) * gs0 + gb0;
                    v1 = ea.y + (v1 + eh.y) * gs1 + gb1;
                } else if (mode == 3) {
                    float2 ea = *(const float2*)&epA[(size_t)r * ld + cc];
                    float2 eh = *(const float2*)&epH[(size_t)r * ld + cc];
                    v0 = fmaxf((ea.x + v0) * gs0 + gb0 + eh.x, 0.f);
                    v1 = fmaxf((ea.y + v1) * gs1 + gb1 + eh.y, 0.f);
                }
                *(float2*)&Cp[(size_t)r * ld + cc] = make_float2(v0, v1);
            }
        }
    }
}

// standalone tf32 GEMM
__global__ void __launch_bounds__(256) gemm_tf32(
        const float* __restrict__ A,
        const float* __restrict__ B1, const float* __restrict__ bias1,
        float* __restrict__ C1, int M1,
        const float* __restrict__ B2, const float* __restrict__ bias2,
        float* __restrict__ C2, int M2,
        int K, int mode,
        const float* __restrict__ epA, const float* __restrict__ epH,
        const float* __restrict__ epG, const float* __restrict__ epB) {
    __shared__ float As[2][64][36];
    __shared__ float Bs[2][64][36];
    gemm_core(As, Bs, blockIdx.x, blockIdx.y, A, B1, bias1, C1, M1,
              B2, bias2, C2, M2, K, mode, epA, epH, epG, epB);
}

// fused: [0,128) input GEMM, [128,192) CSR hist, [192,200) asv precompute
__global__ void __launch_bounds__(256) fused_ingemm_hist(
        const int* __restrict__ ei,
        const float* __restrict__ x,
        const float* __restrict__ w_in, const float* __restrict__ b_in,
        float* __restrict__ C,
        const float* __restrict__ w_gat,
        const float* __restrict__ att_src, const float* __restrict__ att_dst) {
    __shared__ __align__(16) char smbuf[2 * 64 * 36 * 4 * 2];
    const int t = threadIdx.x;
    if (blockIdx.x < 128) {
        float (*As)[64][36] = (float(*)[64][36])smbuf;
        float (*Bs)[64][36] = (float(*)[64][36])(smbuf + 2 * 64 * 36 * 4);
        gemm_core(As, Bs, blockIdx.x & 1, blockIdx.x >> 1, x, w_in, b_in, C, Hh,
                  nullptr, nullptr, nullptr, 0, IND, 1,
                  nullptr, nullptr, nullptr, nullptr);
    } else if (blockIdx.x < 192) {
        int* hist = (int*)smbuf;
        for (int i = t; i < Nn; i += 256) hist[i] = 0;
        __syncthreads();
        const int base = (blockIdx.x - 128) * 4096;
        #pragma unroll 4
        for (int i = t; i < 4096; i += 256)
            atomicAdd(&hist[ei[Ee + base + i]], 1);
        __syncthreads();
        for (int i = t; i < Nn; i += 256) {
            int v = hist[i];
            if (v) atomicAdd(&g_cnt[i], v);
        }
    } else {
        // asv[l][sd][h][c] = sum_d a[l][h][d] * w_gat[l][(h*32+d)][c]
        int i = (blockIdx.x - 192) * 256 + t;          // 0..2047
        int c  = i & 127;
        int h  = (i >> 7) & 3;
        int sd = (i >> 9) & 1;
        int l  = i >> 10;
        const float* av = (sd == 0 ? att_src : att_dst) + l * Hh + h * DHd;
        const float* wg = w_gat + (size_t)l * Hh * Hh + (size_t)(h * DHd) * Hh + c;
        float s = 0.0f;
        #pragma unroll
        for (int d = 0; d < DHd; d++)
            s = fmaf(av[d], wg[(size_t)d * Hh], s);
        g_asv[i] = s;
    }
}

// fused per-layer projection:
//  [0,512): GAT+QKV GEMM   [512,640): alsd mat-vec   [640,640+Ee/256): scatter (l==0)
__global__ void __launch_bounds__(256) fused_proj(
        const int* __restrict__ ei, int do_scatter, int layer,
        const float* __restrict__ A,
        const float* __restrict__ w_gat,
        const float* __restrict__ w_qkv, const float* __restrict__ b_qkv,
        float* __restrict__ Cxp, float* __restrict__ Cqkv) {
    __shared__ float As[2][64][36];
    __shared__ float Bs[2][64][36];
    if (blockIdx.x < 512) {
        gemm_core(As, Bs, blockIdx.x & 7, blockIdx.x >> 3, A,
                  w_gat, nullptr, Cxp, Hh,
                  w_qkv, b_qkv, Cqkv, 3 * Hh,
                  Hh, 0, nullptr, nullptr, nullptr, nullptr);
    } else if (blockIdx.x < 640) {
        // alsd: thread -> (n, j): j = sd*4+h; dot(h[n,:], asv[layer][sd][h][:])
        int i = (blockIdx.x - 512) * 256 + threadIdx.x;   // 0..32767
        int j = i & 7;
        int n = i >> 3;
        const float4* hr = (const float4*)&A[(size_t)n * Hh];
        int sd = j >> 2, h = j & 3;
        const float4* av = (const float4*)&g_asv[((layer * 2 + sd) * NHEADS + h) * Hh];
        float s = 0.0f;
        #pragma unroll
        for (int q = 0; q < 32; q++) {
            float4 a = hr[q], b = av[q];
            s += a.x*b.x + a.y*b.y + a.z*b.z + a.w*b.w;
        }
        g_alsd[n * 8 + j] = s;
    } else if (do_scatter) {
        int e = (blockIdx.x - 640) * 256 + threadIdx.x;
        if (e < Ee) {
            int d = ei[Ee + e];
            int pos = atomicAdd(&g_cursor[d], 1);
            g_srcs[pos] = ei[e];
        }
    }
}

__global__ void csr_scan() {
    __shared__ int sm[1024];
    int t = threadIdx.x;
    int b = t * 4;
    int c0 = g_cnt[b], c1 = g_cnt[b+1], c2 = g_cnt[b+2], c3 = g_cnt[b+3];
    int s1 = c0 + c1, s2 = s1 + c2, s3 = s2 + c3;
    sm[t] = s3;
    __syncthreads();
    for (int off = 1; off < 1024; off <<= 1) {
        int v = (t >= off) ? sm[t - off] : 0;
        __syncthreads();
        sm[t] += v;
        __syncthreads();
    }
    int excl = sm[t] - s3;
    g_rowptr[b]   = excl;
    g_rowptr[b+1] = excl + c0;
    g_rowptr[b+2] = excl + s1;
    g_rowptr[b+3] = excl + s2;
    g_cursor[b]   = excl;
    g_cursor[b+1] = excl + c0;
    g_cursor[b+2] = excl + s1;
    g_cursor[b+3] = excl + s2;
    if (t == 1023) g_rowptr[Nn] = sm[1023];
}

// ---------------- output projection: warp per node, M=2 ----------------------
__global__ void __launch_bounds__(256) out_proj(
        const float* __restrict__ hsrc, const float* __restrict__ w_out,
        const float* __restrict__ b_out, float* __restrict__ out) {
    const int warp = threadIdx.x >> 5, lane = threadIdx.x & 31;
    const int n = blockIdx.x * 8 + warp;
    float4 h4 = *(const float4*)&hsrc[(size_t)n * Hh + lane * 4];
    float4 w0 = *(const float4*)&w_out[lane * 4];
    float4 w1 = *(const float4*)&w_out[Hh + lane * 4];
    float s0 = h4.x*w0.x + h4.y*w0.y + h4.z*w0.z + h4.w*w0.w;
    float s1 = h4.x*w1.x + h4.y*w1.y + h4.z*w1.z + h4.w*w1.w;
    #pragma unroll
    for (int off = 16; off > 0; off >>= 1) {
        s0 += __shfl_xor_sync(0xffffffffu, s0, off);
        s1 += __shfl_xor_sync(0xffffffffu, s1, off);
    }
    if (lane == 0) {
        out[n * 2]     = s0 + b_out[0];
        out[n * 2 + 1] = s1 + b_out[1];
    }
}

__device__ __forceinline__ float leaky(float x) { return x >= 0.0f ? x : 0.2f * x; }

struct FlashSmem {
    float Ks[64][36];
    float Vs[64][40];
    float Ps[4][16][68];   // 64 cols + 4 pad — P is 16x64 per warp (do NOT shrink)
};

// ---------------- FAT kernel: blocks [0,1024) = flash, [1024,5120) = GAT -----
__global__ void __launch_bounds__(128) gat_flash(
        const float* __restrict__ bias, const float* __restrict__ g0,
        const float* __restrict__ b0) {
    __shared__ FlashSmem sm;
    __shared__ int s_last;
    const int t = threadIdx.x;
    const float NEGINF = -__int_as_float(0x7f800000);

    if (blockIdx.x < FLASHBLK) {
        const int fb = blockIdx.x;
        const int qt = fb & 63;
        const int hd = (fb >> 6) & 3;
        const int sp = fb >> 8;
        const int w = t >> 5, lane = t & 31;
        const int gi = lane >> 2, li = lane & 3;
        const int q0 = qt * 64 + w * 16;
        const int kbase = sp * (Nn / KSPLIT);

        unsigned qa[4][4];
        {
            // 1/sqrt(32) * log2(e): scores land in log2 domain
            const float scq = 0.17677669529663687f * 1.4426950408889634f;
            #pragma unroll
            for (int ks = 0; ks < 4; ks++) {
                int c = hd * 32 + ks * 8 + li;
                qa[ks][0] = tf32u(g_qkv[(q0+gi  )*384 + c] * scq);
                qa[ks][1] = tf32u(g_qkv[(q0+gi+8)*384 + c] * scq);
                qa[ks][2] = tf32u(g_qkv[(q0+gi  )*384 + c+4] * scq);
                qa[ks][3] = tf32u(g_qkv[(q0+gi+8)*384 + c+4] * scq);
            }
        }

        // cp.async staging (no register staging -> lower reg pressure)
        auto stage_tile = [&](int ti) {
            int kb = kbase + ti * 64;
            #pragma unroll
            for (int i = 0; i < 4; i++) {
                int c = t + i * 128;
                int j = c >> 3, d4 = c & 7;
                const float* p = &g_qkv[(kb + j) * 384 + 128 + hd * 32 + d4 * 4];
                cpa16(&sm.Ks[j][d4 * 4], p);
                cpa16(&sm.Vs[j][d4 * 4], p + 128);
            }
            asm volatile("cp.async.commit_group;");
        };
        // in-place tf32 rounding of the chunks this thread staged
        auto convert_tile = [&]() {
            #pragma unroll
            for (int i = 0; i < 4; i++) {
                int c = t + i * 128;
                int j = c >> 3, d4 = c & 7;
                float4 k4 = *(float4*)&sm.Ks[j][d4 * 4];
                k4.x = tf32f(k4.x); k4.y = tf32f(k4.y); k4.z = tf32f(k4.z); k4.w = tf32f(k4.w);
                *(float4*)&sm.Ks[j][d4 * 4] = k4;
                float4 v4 = *(float4*)&sm.Vs[j][d4 * 4];
                v4.x = tf32f(v4.x); v4.y = tf32f(v4.y); v4.z = tf32f(v4.z); v4.w = tf32f(v4.w);
                *(float4*)&sm.Vs[j][d4 * 4] = v4;
            }
        };

        float mxl = NEGINF, mxh = NEGINF, lsl = 0.0f, lsh = 0.0f;
        float o[4][4];
        #pragma unroll
        for (int jn = 0; jn < 4; jn++)
            #pragma unroll
            for (int i = 0; i < 4; i++) o[jn][i] = 0.0f;

        stage_tile(0);
        for (int ti = 0; ti < NTILES; ti++) {
            asm volatile("cp.async.wait_group 0;");
            __syncthreads();
            convert_tile();
            __syncthreads();

            float s[8][4];
            #pragma unroll
            for (int jk = 0; jk < 8; jk++) {
                s[jk][0] = s[jk][1] = s[jk][2] = s[jk][3] = 0.0f;
                #pragma unroll
                for (int ks = 0; ks < 4; ks++) {
                    unsigned b0v = __float_as_uint(sm.Ks[jk*8+gi][ks*8+li]);
                    unsigned b1v = __float_as_uint(sm.Ks[jk*8+gi][ks*8+li+4]);
                    mma_tf32(s[jk], qa[ks], b0v, b1v);
                }
            }
            float tml = NEGINF, tmh = NEGINF;
            #pragma unroll
            for (int jk = 0; jk < 8; jk++) {
                tml = fmaxf(tml, fmaxf(s[jk][0], s[jk][1]));
                tmh = fmaxf(tmh, fmaxf(s[jk][2], s[jk][3]));
            }
            tml = fmaxf(tml, __shfl_xor_sync(0xffffffffu, tml, 1));
            tml = fmaxf(tml, __shfl_xor_sync(0xffffffffu, tml, 2));
            tmh = fmaxf(tmh, __shfl_xor_sync(0xffffffffu, tmh, 1));
            tmh = fmaxf(tmh, __shfl_xor_sync(0xffffffffu, tmh, 2));
            float nml = fmaxf(mxl, tml), nmh = fmaxf(mxh, tmh);
            float scl = ex2(mxl - nml), sch = ex2(mxh - nmh);
            mxl = nml; mxh = nmh;
            lsl *= scl; lsh *= sch;
            #pragma unroll
            for (int jn = 0; jn < 4; jn++) {
                o[jn][0] *= scl; o[jn][1] *= scl;
                o[jn][2] *= sch; o[jn][3] *= sch;
            }
            float rsl = 0.0f, rsh = 0.0f;
            #pragma unroll
            for (int jk = 0; jk < 8; jk++) {
                float p0 = ex2(s[jk][0] - mxl), p1 = ex2(s[jk][1] - mxl);
                float p2 = ex2(s[jk][2] - mxh), p3 = ex2(s[jk][3] - mxh);
                rsl += p0 + p1; rsh += p2 + p3;
                float2 lo = make_float2(tf32f(p0), tf32f(p1));
                float2 hi = make_float2(tf32f(p2), tf32f(p3));
                *(float2*)&sm.Ps[w][gi  ][jk*8 + 2*li] = lo;
                *(float2*)&sm.Ps[w][gi+8][jk*8 + 2*li] = hi;
            }
            rsl += __shfl_xor_sync(0xffffffffu, rsl, 1);
            rsl += __shfl_xor_sync(0xffffffffu, rsl, 2);
            rsh += __shfl_xor_sync(0xffffffffu, rsh, 1);
            rsh += __shfl_xor_sync(0xffffffffu, rsh, 2);
            lsl += rsl; lsh += rsh;
            __syncwarp();
            #pragma unroll
            for (int kk = 0; kk < 8; kk++) {
                unsigned pa[4];
                pa[0] = __float_as_uint(sm.Ps[w][gi  ][kk*8 + li]);
                pa[1] = __float_as_uint(sm.Ps[w][gi+8][kk*8 + li]);
                pa[2] = __float_as_uint(sm.Ps[w][gi  ][kk*8 + li + 4]);
                pa[3] = __float_as_uint(sm.Ps[w][gi+8][kk*8 + li + 4]);
                #pragma unroll
                for (int jn = 0; jn < 4; jn++) {
                    unsigned b0v = __float_as_uint(sm.Vs[kk*8+li  ][jn*8+gi]);
                    unsigned b1v = __float_as_uint(sm.Vs[kk*8+li+4][jn*8+gi]);
                    mma_tf32(o[jn], pa, b0v, b1v);
                }
            }
            __syncthreads();           // all warps done with K/V before restaging
            if (ti + 1 < NTILES) stage_tile(ti + 1);
        }

        const int nl = q0 + gi, nh = nl + 8;
        const int qhl = nl * 4 + hd, qhh = nh * 4 + hd;
        if (li == 0) {
            g_pm[sp * NQH + qhl] = mxl;    // log2 domain
            g_pl[sp * NQH + qhl] = lsl;
            g_pm[sp * NQH + qhh] = mxh;
            g_pl[sp * NQH + qhh] = lsh;
        }
        #pragma unroll
        for (int jn = 0; jn < 4; jn++) {
            int dh = jn * 8 + 2 * li;
            *(float2*)&g_pacc[((size_t)sp * NQH + qhl) * DHd + dh] = make_float2(o[jn][0], o[jn][1]);
            *(float2*)&g_pacc[((size_t)sp * NQH + qhh) * DHd + dh] = make_float2(o[jn][2], o[jn][3]);
        }

        // ---- fused split-K merge (log2-domain weights); tick self-resets ----
        __threadfence();
        if (t == 0) {
            int v = atomicAdd(&g_tick[(qt << 2) | hd], 1);
            s_last = (v == KSPLIT - 1);
            if (s_last) g_tick[(qt << 2) | hd] = 0;
        }
        __syncthreads();
        if (s_last) {
            for (int i = t; i < 64 * DHd; i += 128) {
                int q = i >> 5, dd = i & 31;
                int n = qt * 64 + q;
                int qh = n * 4 + hd;
                float m0 = g_pm[0*NQH+qh], m1 = g_pm[1*NQH+qh];
                float m2 = g_pm[2*NQH+qh], m3 = g_pm[3*NQH+qh];
                float M = fmaxf(fmaxf(m0, m1), fmaxf(m2, m3));
                float w0 = ex2(m0 - M), w1 = ex2(m1 - M);
                float w2 = ex2(m2 - M), w3 = ex2(m3 - M);
                float L = g_pl[0*NQH+qh]*w0 + g_pl[1*NQH+qh]*w1
                        + g_pl[2*NQH+qh]*w2 + g_pl[3*NQH+qh]*w3;
                float a = g_pacc[((size_t)0*NQH+qh)*DHd + dd] * w0
                        + g_pacc[((size_t)1*NQH+qh)*DHd + dd] * w1
                        + g_pacc[((size_t)2*NQH+qh)*DHd + dd] * w2
                        + g_pacc[((size_t)3*NQH+qh)*DHd + dd] * w3;
                g_attn[n * Hh + hd * DHd + dd] = a / L;
            }
        }
    } else {
        // =========== GAT aggregation: warp w = head w, lane = channel ===========
        const int d = blockIdx.x - FLASHBLK;
        const int w = t >> 5, lane = t & 31;
        const int beg = g_rowptr[d], end = g_rowptr[d + 1];
        const float adh = g_alsd[d * 8 + 4 + w];

        float mx = NEGINF;
        for (int e = beg + lane; e < end; e += 32) {
            int s = g_srcs[e];
            mx = fmaxf(mx, leaky(g_alsd[s * 8 + w] + adh));
        }
        #pragma unroll
        for (int off = 16; off > 0; off >>= 1)
            mx = fmaxf(mx, __shfl_xor_sync(0xffffffffu, mx, off));

        float den = 0.0f;
        float acc = 0.0f;
        const int c = w * 32 + lane;
        for (int cb = beg; cb < end; cb += 32) {
            int cnt = min(32, end - cb);
            int e = cb + lane;
            float wgt = 0.0f;
            int ssrc = 0;
            if (lane < cnt) {
                ssrc = g_srcs[e];
                wgt = __expf(leaky(g_alsd[ssrc * 8 + w] + adh) - mx);
            }
            den += wgt;
            for (int j = 0; j < cnt; j++) {
                float wj = __shfl_sync(0xffffffffu, wgt, j);
                int sj   = __shfl_sync(0xffffffffu, ssrc, j);
                acc = fmaf(wj, g_xp[sj * Hh + c], acc);
            }
        }
        #pragma unroll
        for (int off = 16; off > 0; off >>= 1)
            den += __shfl_xor_sync(0xffffffffu, den, off);

        float v = acc / (den + 1e-16f) + bias[c] + g_h[d * Hh + c];
        g_hloc[d * Hh + c] = v * bn_scale(g0[c]) + b0[c];
    }
}

// ---------------- host launch ----------------
extern "C" void kernel_launch(void* const* d_in, const int* in_sizes, int n_in,
                              void* d_out, int out_size) {
    const float* x       = (const float*)d_in[0];
    const int*   ei      = (const int*)d_in[1];
    const float* w_in    = (const float*)d_in[2];
    const float* b_in    = (const float*)d_in[3];
    const float* w_gat   = (const float*)d_in[4];
    const float* att_src = (const float*)d_in[5];
    const float* att_dst = (const float*)d_in[6];
    const float* b_gat   = (const float*)d_in[7];
    const float* w_qkv   = (const float*)d_in[8];
    const float* b_qkv   = (const float*)d_in[9];
    const float* w_o     = (const float*)d_in[10];
    const float* b_o     = (const float*)d_in[11];
    const float* bn_g    = (const float*)d_in[12];
    const float* bn_b    = (const float*)d_in[13];
    const float* w1      = (const float*)d_in[14];
    const float* b1      = (const float*)d_in[15];
    const float* w2      = (const float*)d_in[16];
    const float* b2      = (const float*)d_in[17];
    const float* w_out   = (const float*)d_in[18];
    const float* b_out   = (const float*)d_in[19];
    float* out = (float*)d_out;

    float *p_h, *p_xp, *p_qkv, *p_attn, *p_out, *p_t1, *p_hloc;
    int* p_cnt;
    cudaGetSymbolAddress((void**)&p_h,    g_h);
    cudaGetSymbolAddress((void**)&p_xp,   g_xp);
    cudaGetSymbolAddress((void**)&p_qkv,  g_qkv);
    cudaGetSymbolAddress((void**)&p_attn, g_attn);
    cudaGetSymbolAddress((void**)&p_out,  g_out);
    cudaGetSymbolAddress((void**)&p_t1,   g_t1);
    cudaGetSymbolAddress((void**)&p_hloc, g_hloc);
    cudaGetSymbolAddress((void**)&p_cnt,  g_cnt);

    // CSR count + input projection + asv precompute overlapped
    cudaMemsetAsync(p_cnt, 0, Nn * sizeof(int));
    fused_ingemm_hist<<<200, 256>>>(ei, x, w_in, b_in, p_h, w_gat, att_src, att_dst);
    csr_scan<<<1, 1024>>>();

    for (int l = 0; l < Ll; l++) {
        // projection: GAT+QKV GEMM + alsd mat-vec (+ CSR scatter for l==0)
        int nblk = 640 + (l == 0 ? Ee / 256 : 0);
        fused_proj<<<nblk, 256>>>(ei, l == 0, l, p_h,
                                  w_gat + l * Hh * Hh,
                                  w_qkv + l * 3 * Hh * Hh, b_qkv + l * 3 * Hh,
                                  p_xp, p_qkv);

        // FAT kernel: flash attention (split-K merge fused) + GAT aggregation
        gat_flash<<<FLASHBLK + Nn, 128>>>(b_gat + l * Hh,
                                          bn_g + (l * 3 + 0) * Hh, bn_b + (l * 3 + 0) * Hh);

        // w_o GEMM with fused combine_att epilogue -> g_out
        gemm_tf32<<<dim3(2, 64), 256>>>(p_attn, w_o + l * Hh * Hh, b_o + l * Hh, p_out, Hh,
                                        nullptr, nullptr, nullptr, 0, Hh, 2,
                                        p_hloc, p_h,
                                        bn_g + (l * 3 + 1) * Hh, bn_b + (l * 3 + 1) * Hh);

        // MLP
        gemm_tf32<<<dim3(4, 64), 256>>>(p_out, w1 + l * 2 * Hh * Hh, b1 + l * 2 * Hh, p_t1, 2 * Hh,
                                        nullptr, nullptr, nullptr, 0, Hh, 1,
                                        nullptr, nullptr, nullptr, nullptr);
        // w2 GEMM with fused final_combine epilogue -> g_h
        gemm_tf32<<<dim3(2, 64), 256>>>(p_t1, w2 + l * 2 * Hh * Hh, b2 + l * Hh, p_h, Hh,
                                        nullptr, nullptr, nullptr, 0, 2 * Hh, 3,
                                        p_out, p_h,
                                        bn_g + (l * 3 + 2) * Hh, bn_b + (l * 3 + 2) * Hh);
    }

    // output projection -> [4096, 2]
    out_proj<<<Nn / 8, 256>>>(p_h, w_out, b_out, out);
}

// round 13
// speedup vs baseline: 1.1684x; 1.0538x over previous
#include <cuda_runtime.h>
#include <math.h>

#define Nn 4096
#define Ee 262144
#define IND 64
#define Hh 128
#define NHEADS 4
#define DHd 32
#define Ll 2
#define KSPLIT 4
#define NQH (Nn * NHEADS)
#define FLASHBLK ((Nn / 64) * NHEADS * KSPLIT)   // 1024
#define NTILES ((Nn / KSPLIT) / 64)              // 16
#define LOG2E 1.4426950408889634f

typedef unsigned long long ull;

// ---------------- scratch (static device globals; no allocation) -------------
__device__ float g_h[Nn*Hh];
__device__ float g_xp[Nn*Hh];
__device__ float g_alsd[Nn*8];          // log2-scaled: [n][0..3]=als, [4..7]=ald
__device__ float g_asv[Ll*2*NHEADS*Hh]; // log2-scaled attention vectors
__device__ unsigned g_mxals[Ll*NHEADS]; // ordered-uint per-head global max of als (scaled)
__device__ float g_hloc[Nn*Hh];
__device__ float g_qkv[Nn*3*Hh];
__device__ float g_attn[Nn*Hh];
__device__ float g_out[Nn*Hh];
__device__ float g_t1[Nn*2*Hh];
// flash split-K partials
__device__ float g_pm[KSPLIT*NQH];
__device__ float g_pl[KSPLIT*NQH];
__device__ float g_pacc[KSPLIT*NQH*DHd];
__device__ int   g_tick[256];           // zero-init; self-resetting
// CSR
__device__ int g_cnt[Nn];
__device__ int g_cursor[Nn];
__device__ int g_rowptr[Nn+1];
__device__ int g_srcs[Ee];

__device__ __forceinline__ float bn_scale(float g) { return g * rsqrtf(1.0f + 1e-5f); }

__device__ __forceinline__ float ex2(float x) {
    float r; asm("ex2.approx.f32 %0,%1;" : "=f"(r) : "f"(x)); return r;
}
__device__ __forceinline__ void cpa16(void* sdst, const void* gsrc) {
    unsigned s = (unsigned)__cvta_generic_to_shared(sdst);
    asm volatile("cp.async.cg.shared.global [%0],[%1],16;" :: "r"(s), "l"(gsrc));
}
// monotone float<->uint ordering for atomicMax
__device__ __forceinline__ unsigned oenc(float f) {
    unsigned u = __float_as_uint(f);
    return (u & 0x80000000u) ? ~u : (u | 0x80000000u);
}
__device__ __forceinline__ float odec(unsigned k) {
    unsigned u = (k & 0x80000000u) ? (k & 0x7fffffffu) : ~k;
    return __uint_as_float(u);
}

// ---- tf32 helpers ----
__device__ __forceinline__ unsigned tf32u(float f) {
    unsigned r; asm("cvt.rna.tf32.f32 %0,%1;" : "=r"(r) : "f"(f)); return r;
}
__device__ __forceinline__ float tf32f(float f) {
    return __uint_as_float(tf32u(f));
}
__device__ __forceinline__ void mma_tf32(float* d, const unsigned* a, unsigned b0, unsigned b1) {
    asm volatile(
        "mma.sync.aligned.m16n8k8.row.col.f32.tf32.tf32.f32 "
        "{%0,%1,%2,%3},{%4,%5,%6,%7},{%8,%9},{%0,%1,%2,%3};"
        : "+f"(d[0]), "+f"(d[1]), "+f"(d[2]), "+f"(d[3])
        : "r"(a[0]), "r"(a[1]), "r"(a[2]), "r"(a[3]), "r"(b0), "r"(b1));
}

// ---------------- tf32 GEMM core (64x64 tile, cp.async double-buffered) ------
__device__ __forceinline__ void gemm_core(
        float (*As)[64][36], float (*Bs)[64][36], int bx, int by,
        const float* __restrict__ A,
        const float* __restrict__ B1, const float* __restrict__ bias1,
        float* __restrict__ C1, int M1,
        const float* __restrict__ B2, const float* __restrict__ bias2,
        float* __restrict__ C2, int M2,
        int K, int mode,
        const float* __restrict__ epA, const float* __restrict__ epH,
        const float* __restrict__ epG, const float* __restrict__ epB) {
    const int t = threadIdx.x;
    const int w = t >> 5, lane = t & 31;
    const int gi = lane >> 2, li = lane & 3;
    const int wr = w >> 2, wc = w & 3;
    const int r0 = by * 64;
    const int c0 = bx * 64;
    const int row_s = t >> 3;
    const int kq4 = (t & 7) * 4;

    float o[2][2][4];
    #pragma unroll
    for (int mt = 0; mt < 2; mt++)
        #pragma unroll
        for (int nt = 0; nt < 2; nt++)
            #pragma unroll
            for (int i = 0; i < 4; i++) o[mt][nt][i] = 0.0f;

    auto stage = [&](int kc, int buf) {
        #pragma unroll
        for (int i = 0; i < 2; i++) {
            int row = row_s + i * 32;
            cpa16(&As[buf][row][kq4], &A[(size_t)(r0 + row) * K + kc + kq4]);
            int cc = c0 + row;
            const float* Brow = (cc < M1) ? (B1 + (size_t)cc * K)
                                          : (B2 + (size_t)(cc - M1) * K);
            cpa16(&Bs[buf][row][kq4], &Brow[kc + kq4]);
        }
        asm volatile("cp.async.commit_group;");
    };

    const int nc = K >> 5;
    stage(0, 0);
    for (int ci = 0; ci < nc; ci++) {
        int buf = ci & 1;
        if (ci + 1 < nc) {
            stage((ci + 1) << 5, buf ^ 1);
            asm volatile("cp.async.wait_group 1;");
        } else {
            asm volatile("cp.async.wait_group 0;");
        }
        __syncthreads();
        #pragma unroll
        for (int k8 = 0; k8 < 32; k8 += 8) {
            unsigned a[2][4];
            #pragma unroll
            for (int mt = 0; mt < 2; mt++) {
                int row = wr * 32 + mt * 16;
                a[mt][0] = tf32u(As[buf][row + gi    ][k8 + li]);
                a[mt][1] = tf32u(As[buf][row + gi + 8][k8 + li]);
                a[mt][2] = tf32u(As[buf][row + gi    ][k8 + li + 4]);
                a[mt][3] = tf32u(As[buf][row + gi + 8][k8 + li + 4]);
            }
            unsigned b[2][2];
            #pragma unroll
            for (int nt = 0; nt < 2; nt++) {
                int col = wc * 16 + nt * 8;
                b[nt][0] = tf32u(Bs[buf][col + gi][k8 + li]);
                b[nt][1] = tf32u(Bs[buf][col + gi][k8 + li + 4]);
            }
            #pragma unroll
            for (int mt = 0; mt < 2; mt++)
                #pragma unroll
                for (int nt = 0; nt < 2; nt++)
                    mma_tf32(o[mt][nt], a[mt], b[nt][0], b[nt][1]);
        }
        __syncthreads();
    }

    #pragma unroll
    for (int nt = 0; nt < 2; nt++) {
        int c = c0 + wc * 16 + nt * 8 + 2 * li;
        const float* bias; float* Cp; int ld, cc;
        if (c < M1) { bias = bias1; Cp = C1; ld = M1; cc = c; }
        else        { bias = bias2; Cp = C2; ld = M2; cc = c - M1; }
        float b0v = bias ? bias[cc] : 0.0f;
        float b1v = bias ? bias[cc + 1] : 0.0f;
        float gs0 = 0.f, gs1 = 0.f, gb0 = 0.f, gb1 = 0.f;
        if (mode >= 2) {
            gs0 = bn_scale(epG[c]); gs1 = bn_scale(epG[c + 1]);
            gb0 = epB[c]; gb1 = epB[c + 1];
        }
        #pragma unroll
        for (int mt = 0; mt < 2; mt++) {
            #pragma unroll
            for (int half = 0; half < 2; half++) {
                int r = r0 + wr * 32 + mt * 16 + gi + half * 8;
                float v0 = o[mt][nt][half * 2]     + b0v;
                float v1 = o[mt][nt][half * 2 + 1] + b1v;
                if (mode == 1) { v0 = fmaxf(v0, 0.f); v1 = fmaxf(v1, 0.f); }
                else if (mode == 2) {
                    float2 ea = *(const float2*)&epA[(size_t)r * ld + cc];
                    float2 eh = *(const float2*)&epH[(size_t)r * ld + cc];
                    v0 = ea.x + (v0 + eh.x) * gs0 + gb0;
                    v1 = ea.y + (v1 + eh.y) * gs1 + gb1;
                } else if (mode == 3) {
                    float2 ea = *(const float2*)&epA[(size_t)r * ld + cc];
                    float2 eh = *(const float2*)&epH[(size_t)r * ld + cc];
                    v0 = fmaxf((ea.x + v0) * gs0 + gb0 + eh.x, 0.f);
                    v1 = fmaxf((ea.y + v1) * gs1 + gb1 + eh.y, 0.f);
                }
                *(float2*)&Cp[(size_t)r * ld + cc] = make_float2(v0, v1);
            }
        }
    }
}

// standalone tf32 GEMM
__global__ void __launch_bounds__(256) gemm_tf32(
        const float* __restrict__ A,
        const float* __restrict__ B1, const float* __restrict__ bias1,
        float* __restrict__ C1, int M1,
        const float* __restrict__ B2, const float* __restrict__ bias2,
        float* __restrict__ C2, int M2,
        int K, int mode,
        const float* __restrict__ epA, const float* __restrict__ epH,
        const float* __restrict__ epG, const float* __restrict__ epB) {
    __shared__ float As[2][64][36];
    __shared__ float Bs[2][64][36];
    gemm_core(As, Bs, blockIdx.x, blockIdx.y, A, B1, bias1, C1, M1,
              B2, bias2, C2, M2, K, mode, epA, epH, epG, epB);
}

// fused: [0,128) input GEMM, [128,192) CSR hist, [192,200) asv precompute
__global__ void __launch_bounds__(256) fused_ingemm_hist(
        const int* __restrict__ ei,
        const float* __restrict__ x,
        const float* __restrict__ w_in, const float* __restrict__ b_in,
        float* __restrict__ C,
        const float* __restrict__ w_gat,
        const float* __restrict__ att_src, const float* __restrict__ att_dst) {
    __shared__ __align__(16) char smbuf[2 * 64 * 36 * 4 * 2];
    const int t = threadIdx.x;
    if (blockIdx.x < 128) {
        float (*As)[64][36] = (float(*)[64][36])smbuf;
        float (*Bs)[64][36] = (float(*)[64][36])(smbuf + 2 * 64 * 36 * 4);
        gemm_core(As, Bs, blockIdx.x & 1, blockIdx.x >> 1, x, w_in, b_in, C, Hh,
                  nullptr, nullptr, nullptr, 0, IND, 1,
                  nullptr, nullptr, nullptr, nullptr);
    } else if (blockIdx.x < 192) {
        int* hist = (int*)smbuf;
        for (int i = t; i < Nn; i += 256) hist[i] = 0;
        __syncthreads();
        const int base = (blockIdx.x - 128) * 4096;
        #pragma unroll 4
        for (int i = t; i < 4096; i += 256)
            atomicAdd(&hist[ei[Ee + base + i]], 1);
        __syncthreads();
        for (int i = t; i < Nn; i += 256) {
            int v = hist[i];
            if (v) atomicAdd(&g_cnt[i], v);
        }
    } else {
        // asv[l][sd][h][c] = log2e * sum_d a[l][h][d] * w_gat[l][(h*32+d)][c]
        int i = (blockIdx.x - 192) * 256 + t;          // 0..2047
        int c  = i & 127;
        int h  = (i >> 7) & 3;
        int sd = (i >> 9) & 1;
        int l  = i >> 10;
        const float* av = (sd == 0 ? att_src : att_dst) + l * Hh + h * DHd;
        const float* wg = w_gat + (size_t)l * Hh * Hh + (size_t)(h * DHd) * Hh + c;
        float s = 0.0f;
        #pragma unroll
        for (int d = 0; d < DHd; d++)
            s = fmaf(av[d], wg[(size_t)d * Hh], s);
        g_asv[i] = s * LOG2E;
    }
}

// fused per-layer projection:
//  [0,512): GAT+QKV GEMM   [512,640): alsd mat-vec (+per-head als max)
//  [640,640+Ee/256): scatter (l==0)
__global__ void __launch_bounds__(256) fused_proj(
        const int* __restrict__ ei, int do_scatter, int layer,
        const float* __restrict__ A,
        const float* __restrict__ w_gat,
        const float* __restrict__ w_qkv, const float* __restrict__ b_qkv,
        float* __restrict__ Cxp, float* __restrict__ Cqkv) {
    __shared__ float As[2][64][36];
    __shared__ float Bs[2][64][36];
    if (blockIdx.x < 512) {
        gemm_core(As, Bs, blockIdx.x & 7, blockIdx.x >> 3, A,
                  w_gat, nullptr, Cxp, Hh,
                  w_qkv, b_qkv, Cqkv, 3 * Hh,
                  Hh, 0, nullptr, nullptr, nullptr, nullptr);
    } else if (blockIdx.x < 640) {
        // alsd: thread -> (n, j): j = sd*4+h; dot(h[n,:], asv[layer][sd][h][:])
        int i = (blockIdx.x - 512) * 256 + threadIdx.x;   // 0..32767
        int j = i & 7;
        int n = i >> 3;
        const float4* hr = (const float4*)&A[(size_t)n * Hh];
        int sd = j >> 2, h = j & 3;
        const float4* av = (const float4*)&g_asv[((layer * 2 + sd) * NHEADS + h) * Hh];
        float s = 0.0f;
        #pragma unroll
        for (int q = 0; q < 32; q++) {
            float4 a = hr[q], b = av[q];
            s += a.x*b.x + a.y*b.y + a.z*b.z + a.w*b.w;
        }
        g_alsd[n * 8 + j] = s;
        // per-head global max of als (sd==0), warp-reduced then one atomic
        float m = s;
        m = fmaxf(m, __shfl_xor_sync(0xffffffffu, m, 8));
        m = fmaxf(m, __shfl_xor_sync(0xffffffffu, m, 16));
        int lane = threadIdx.x & 31;
        if (sd == 0 && lane < 8)
            atomicMax(&g_mxals[layer * NHEADS + h], oenc(m));
    } else if (do_scatter) {
        int e = (blockIdx.x - 640) * 256 + threadIdx.x;
        if (e < Ee) {
            int d = ei[Ee + e];
            int pos = atomicAdd(&g_cursor[d], 1);
            g_srcs[pos] = ei[e];
        }
    }
}

__global__ void csr_scan() {
    __shared__ int sm[1024];
    int t = threadIdx.x;
    int b = t * 4;
    int c0 = g_cnt[b], c1 = g_cnt[b+1], c2 = g_cnt[b+2], c3 = g_cnt[b+3];
    int s1 = c0 + c1, s2 = s1 + c2, s3 = s2 + c3;
    sm[t] = s3;
    __syncthreads();
    for (int off = 1; off < 1024; off <<= 1) {
        int v = (t >= off) ? sm[t - off] : 0;
        __syncthreads();
        sm[t] += v;
        __syncthreads();
    }
    int excl = sm[t] - s3;
    g_rowptr[b]   = excl;
    g_rowptr[b+1] = excl + c0;
    g_rowptr[b+2] = excl + s1;
    g_rowptr[b+3] = excl + s2;
    g_cursor[b]   = excl;
    g_cursor[b+1] = excl + c0;
    g_cursor[b+2] = excl + s1;
    g_cursor[b+3] = excl + s2;
    if (t == 1023) g_rowptr[Nn] = sm[1023];
}

// ---------------- output projection: warp per node, M=2 ----------------------
__global__ void __launch_bounds__(256) out_proj(
        const float* __restrict__ hsrc, const float* __restrict__ w_out,
        const float* __restrict__ b_out, float* __restrict__ out) {
    const int warp = threadIdx.x >> 5, lane = threadIdx.x & 31;
    const int n = blockIdx.x * 8 + warp;
    float4 h4 = *(const float4*)&hsrc[(size_t)n * Hh + lane * 4];
    float4 w0 = *(const float4*)&w_out[lane * 4];
    float4 w1 = *(const float4*)&w_out[Hh + lane * 4];
    float s0 = h4.x*w0.x + h4.y*w0.y + h4.z*w0.z + h4.w*w0.w;
    float s1 = h4.x*w1.x + h4.y*w1.y + h4.z*w1.z + h4.w*w1.w;
    #pragma unroll
    for (int off = 16; off > 0; off >>= 1) {
        s0 += __shfl_xor_sync(0xffffffffu, s0, off);
        s1 += __shfl_xor_sync(0xffffffffu, s1, off);
    }
    if (lane == 0) {
        out[n * 2]     = s0 + b_out[0];
        out[n * 2 + 1] = s1 + b_out[1];
    }
}

__device__ __forceinline__ float leaky(float x) { return x >= 0.0f ? x : 0.2f * x; }

struct FlashSmem {
    float Ks[64][36];
    float Vs[64][40];
    float Ps[4][16][68];   // 64 cols + 4 pad — P is 16x64 per warp (do NOT shrink)
};

// ---------------- FAT kernel: blocks [0,1024) = flash, [1024,5120) = GAT -----
__global__ void __launch_bounds__(128) gat_flash(
        int layer,
        const float* __restrict__ bias, const float* __restrict__ g0,
        const float* __restrict__ b0) {
    __shared__ FlashSmem sm;
    __shared__ int s_last;
    const int t = threadIdx.x;
    const float NEGINF = -__int_as_float(0x7f800000);

    if (blockIdx.x < FLASHBLK) {
        const int fb = blockIdx.x;
        const int qt = fb & 63;
        const int hd = (fb >> 6) & 3;
        const int sp = fb >> 8;
        const int w = t >> 5, lane = t & 31;
        const int gi = lane >> 2, li = lane & 3;
        const int q0 = qt * 64 + w * 16;
        const int kbase = sp * (Nn / KSPLIT);

        unsigned qa[4][4];
        {
            // 1/sqrt(32) * log2(e): scores land in log2 domain
            const float scq = 0.17677669529663687f * LOG2E;
            #pragma unroll
            for (int ks = 0; ks < 4; ks++) {
                int c = hd * 32 + ks * 8 + li;
                qa[ks][0] = tf32u(g_qkv[(q0+gi  )*384 + c] * scq);
                qa[ks][1] = tf32u(g_qkv[(q0+gi+8)*384 + c] * scq);
                qa[ks][2] = tf32u(g_qkv[(q0+gi  )*384 + c+4] * scq);
                qa[ks][3] = tf32u(g_qkv[(q0+gi+8)*384 + c+4] * scq);
            }
        }

        auto stage_tile = [&](int ti) {
            int kb = kbase + ti * 64;
            #pragma unroll
            for (int i = 0; i < 4; i++) {
                int c = t + i * 128;
                int j = c >> 3, d4 = c & 7;
                const float* p = &g_qkv[(kb + j) * 384 + 128 + hd * 32 + d4 * 4];
                cpa16(&sm.Ks[j][d4 * 4], p);
                cpa16(&sm.Vs[j][d4 * 4], p + 128);
            }
            asm volatile("cp.async.commit_group;");
        };
        auto convert_tile = [&]() {
            #pragma unroll
            for (int i = 0; i < 4; i++) {
                int c = t + i * 128;
                int j = c >> 3, d4 = c & 7;
                float4 k4 = *(float4*)&sm.Ks[j][d4 * 4];
                k4.x = tf32f(k4.x); k4.y = tf32f(k4.y); k4.z = tf32f(k4.z); k4.w = tf32f(k4.w);
                *(float4*)&sm.Ks[j][d4 * 4] = k4;
                float4 v4 = *(float4*)&sm.Vs[j][d4 * 4];
                v4.x = tf32f(v4.x); v4.y = tf32f(v4.y); v4.z = tf32f(v4.z); v4.w = tf32f(v4.w);
                *(float4*)&sm.Vs[j][d4 * 4] = v4;
            }
        };

        float mxl = NEGINF, mxh = NEGINF, lsl = 0.0f, lsh = 0.0f;
        float o[4][4];
        #pragma unroll
        for (int jn = 0; jn < 4; jn++)
            #pragma unroll
            for (int i = 0; i < 4; i++) o[jn][i] = 0.0f;

        stage_tile(0);
        for (int ti = 0; ti < NTILES; ti++) {
            asm volatile("cp.async.wait_group 0;");
            __syncthreads();
            convert_tile();
            __syncthreads();

            float s[8][4];
            #pragma unroll
            for (int jk = 0; jk < 8; jk++) {
                s[jk][0] = s[jk][1] = s[jk][2] = s[jk][3] = 0.0f;
                #pragma unroll
                for (int ks = 0; ks < 4; ks++) {
                    unsigned b0v = __float_as_uint(sm.Ks[jk*8+gi][ks*8+li]);
                    unsigned b1v = __float_as_uint(sm.Ks[jk*8+gi][ks*8+li+4]);
                    mma_tf32(s[jk], qa[ks], b0v, b1v);
                }
            }
            float tml = NEGINF, tmh = NEGINF;
            #pragma unroll
            for (int jk = 0; jk < 8; jk++) {
                tml = fmaxf(tml, fmaxf(s[jk][0], s[jk][1]));
                tmh = fmaxf(tmh, fmaxf(s[jk][2], s[jk][3]));
            }
            tml = fmaxf(tml, __shfl_xor_sync(0xffffffffu, tml, 1));
            tml = fmaxf(tml, __shfl_xor_sync(0xffffffffu, tml, 2));
            tmh = fmaxf(tmh, __shfl_xor_sync(0xffffffffu, tmh, 1));
            tmh = fmaxf(tmh, __shfl_xor_sync(0xffffffffu, tmh, 2));
            float nml = fmaxf(mxl, tml), nmh = fmaxf(mxh, tmh);
            float scl = ex2(mxl - nml), sch = ex2(mxh - nmh);
            mxl = nml; mxh = nmh;
            lsl *= scl; lsh *= sch;
            #pragma unroll
            for (int jn = 0; jn < 4; jn++) {
                o[jn][0] *= scl; o[jn][1] *= scl;
                o[jn][2] *= sch; o[jn][3] *= sch;
            }
            float rsl = 0.0f, rsh = 0.0f;
            #pragma unroll
            for (int jk = 0; jk < 8; jk++) {
                float p0 = ex2(s[jk][0] - mxl), p1 = ex2(s[jk][1] - mxl);
                float p2 = ex2(s[jk][2] - mxh), p3 = ex2(s[jk][3] - mxh);
                rsl += p0 + p1; rsh += p2 + p3;
                float2 lo = make_float2(tf32f(p0), tf32f(p1));
                float2 hi = make_float2(tf32f(p2), tf32f(p3));
                *(float2*)&sm.Ps[w][gi  ][jk*8 + 2*li] = lo;
                *(float2*)&sm.Ps[w][gi+8][jk*8 + 2*li] = hi;
            }
            rsl += __shfl_xor_sync(0xffffffffu, rsl, 1);
            rsl += __shfl_xor_sync(0xffffffffu, rsl, 2);
            rsh += __shfl_xor_sync(0xffffffffu, rsh, 1);
            rsh += __shfl_xor_sync(0xffffffffu, rsh, 2);
            lsl += rsl; lsh += rsh;
            __syncwarp();
            #pragma unroll
            for (int kk = 0; kk < 8; kk++) {
                unsigned pa[4];
                pa[0] = __float_as_uint(sm.Ps[w][gi  ][kk*8 + li]);
                pa[1] = __float_as_uint(sm.Ps[w][gi+8][kk*8 + li]);
                pa[2] = __float_as_uint(sm.Ps[w][gi  ][kk*8 + li + 4]);
                pa[3] = __float_as_uint(sm.Ps[w][gi+8][kk*8 + li + 4]);
                #pragma unroll
                for (int jn = 0; jn < 4; jn++) {
                    unsigned b0v = __float_as_uint(sm.Vs[kk*8+li  ][jn*8+gi]);
                    unsigned b1v = __float_as_uint(sm.Vs[kk*8+li+4][jn*8+gi]);
                    mma_tf32(o[jn], pa, b0v, b1v);
                }
            }
            __syncthreads();           // all warps done with K/V before restaging
            if (ti + 1 < NTILES) stage_tile(ti + 1);
        }

        const int nl = q0 + gi, nh = nl + 8;
        const int qhl = nl * 4 + hd, qhh = nh * 4 + hd;
        if (li == 0) {
            g_pm[sp * NQH + qhl] = mxl;    // log2 domain
            g_pl[sp * NQH + qhl] = lsl;
            g_pm[sp * NQH + qhh] = mxh;
            g_pl[sp * NQH + qhh] = lsh;
        }
        #pragma unroll
        for (int jn = 0; jn < 4; jn++) {
            int dh = jn * 8 + 2 * li;
            *(float2*)&g_pacc[((size_t)sp * NQH + qhl) * DHd + dh] = make_float2(o[jn][0], o[jn][1]);
            *(float2*)&g_pacc[((size_t)sp * NQH + qhh) * DHd + dh] = make_float2(o[jn][2], o[jn][3]);
        }

        // ---- fused split-K merge (log2-domain weights); tick self-resets ----
        __threadfence();
        if (t == 0) {
            int v = atomicAdd(&g_tick[(qt << 2) | hd], 1);
            s_last = (v == KSPLIT - 1);
            if (s_last) g_tick[(qt << 2) | hd] = 0;
        }
        __syncthreads();
        if (s_last) {
            for (int i = t; i < 64 * DHd; i += 128) {
                int q = i >> 5, dd = i & 31;
                int n = qt * 64 + q;
                int qh = n * 4 + hd;
                float m0 = g_pm[0*NQH+qh], m1 = g_pm[1*NQH+qh];
                float m2 = g_pm[2*NQH+qh], m3 = g_pm[3*NQH+qh];
                float M = fmaxf(fmaxf(m0, m1), fmaxf(m2, m3));
                float w0 = ex2(m0 - M), w1 = ex2(m1 - M);
                float w2 = ex2(m2 - M), w3 = ex2(m3 - M);
                float L = g_pl[0*NQH+qh]*w0 + g_pl[1*NQH+qh]*w1
                        + g_pl[2*NQH+qh]*w2 + g_pl[3*NQH+qh]*w3;
                float a = g_pacc[((size_t)0*NQH+qh)*DHd + dd] * w0
                        + g_pacc[((size_t)1*NQH+qh)*DHd + dd] * w1
                        + g_pacc[((size_t)2*NQH+qh)*DHd + dd] * w2
                        + g_pacc[((size_t)3*NQH+qh)*DHd + dd] * w3;
                g_attn[n * Hh + hd * DHd + dd] = a / L;
            }
        }
    } else {
        // ===== GAT aggregation: warp w = head w; global-max shift (no max pass)
        const int d = blockIdx.x - FLASHBLK;
        const int w = t >> 5, lane = t & 31;
        const int beg = g_rowptr[d], end = g_rowptr[d + 1];
        const float adh = g_alsd[d * 8 + 4 + w];           // log2-scaled
        const float mx = leaky(odec(g_mxals[layer * NHEADS + w]) + adh); // upper bound

        float den = 0.0f;
        float acc = 0.0f;
        const int c = w * 32 + lane;
        for (int cb = beg; cb < end; cb += 32) {
            int cnt = min(32, end - cb);
            int e = cb + lane;
            float wgt = 0.0f;
            int ssrc = 0;
            if (lane < cnt) {
                ssrc = g_srcs[e];
                wgt = ex2(leaky(g_alsd[ssrc * 8 + w] + adh) - mx);
            }
            den += wgt;
            for (int j = 0; j < cnt; j++) {
                float wj = __shfl_sync(0xffffffffu, wgt, j);
                int sj   = __shfl_sync(0xffffffffu, ssrc, j);
                acc = fmaf(wj, g_xp[sj * Hh + c], acc);
            }
        }
        #pragma unroll
        for (int off = 16; off > 0; off >>= 1)
            den += __shfl_xor_sync(0xffffffffu, den, off);

        float v = acc / (den + 1e-16f) + bias[c] + g_h[d * Hh + c];
        g_hloc[d * Hh + c] = v * bn_scale(g0[c]) + b0[c];
    }
}

// ---------------- host launch ----------------
extern "C" void kernel_launch(void* const* d_in, const int* in_sizes, int n_in,
                              void* d_out, int out_size) {
    const float* x       = (const float*)d_in[0];
    const int*   ei      = (const int*)d_in[1];
    const float* w_in    = (const float*)d_in[2];
    const float* b_in    = (const float*)d_in[3];
    const float* w_gat   = (const float*)d_in[4];
    const float* att_src = (const float*)d_in[5];
    const float* att_dst = (const float*)d_in[6];
    const float* b_gat   = (const float*)d_in[7];
    const float* w_qkv   = (const float*)d_in[8];
    const float* b_qkv   = (const float*)d_in[9];
    const float* w_o     = (const float*)d_in[10];
    const float* b_o     = (const float*)d_in[11];
    const float* bn_g    = (const float*)d_in[12];
    const float* bn_b    = (const float*)d_in[13];
    const float* w1      = (const float*)d_in[14];
    const float* b1      = (const float*)d_in[15];
    const float* w2      = (const float*)d_in[16];
    const float* b2      = (const float*)d_in[17];
    const float* w_out   = (const float*)d_in[18];
    const float* b_out   = (const float*)d_in[19];
    float* out = (float*)d_out;

    float *p_h, *p_xp, *p_qkv, *p_attn, *p_out, *p_t1, *p_hloc;
    int* p_cnt;
    cudaGetSymbolAddress((void**)&p_h,    g_h);
    cudaGetSymbolAddress((void**)&p_xp,   g_xp);
    cudaGetSymbolAddress((void**)&p_qkv,  g_qkv);
    cudaGetSymbolAddress((void**)&p_attn, g_attn);
    cudaGetSymbolAddress((void**)&p_out,  g_out);
    cudaGetSymbolAddress((void**)&p_t1,   g_t1);
    cudaGetSymbolAddress((void**)&p_hloc, g_hloc);
    cudaGetSymbolAddress((void**)&p_cnt,  g_cnt);

    // CSR count + input projection + asv precompute overlapped
    cudaMemsetAsync(p_cnt, 0, Nn * sizeof(int));
    fused_ingemm_hist<<<200, 256>>>(ei, x, w_in, b_in, p_h, w_gat, att_src, att_dst);
    csr_scan<<<1, 1024>>>();

    for (int l = 0; l < Ll; l++) {
        // projection: GAT+QKV GEMM + alsd mat-vec (+ CSR scatter for l==0)
        int nblk = 640 + (l == 0 ? Ee / 256 : 0);
        fused_proj<<<nblk, 256>>>(ei, l == 0, l, p_h,
                                  w_gat + l * Hh * Hh,
                                  w_qkv + l * 3 * Hh * Hh, b_qkv + l * 3 * Hh,
                                  p_xp, p_qkv);

        // FAT kernel: flash attention (split-K merge fused) + GAT aggregation
        gat_flash<<<FLASHBLK + Nn, 128>>>(l, b_gat + l * Hh,
                                          bn_g + (l * 3 + 0) * Hh, bn_b + (l * 3 + 0) * Hh);

        // w_o GEMM with fused combine_att epilogue -> g_out
        gemm_tf32<<<dim3(2, 64), 256>>>(p_attn, w_o + l * Hh * Hh, b_o + l * Hh, p_out, Hh,
                                        nullptr, nullptr, nullptr, 0, Hh, 2,
                                        p_hloc, p_h,
                                        bn_g + (l * 3 + 1) * Hh, bn_b + (l * 3 + 1) * Hh);

        // MLP
        gemm_tf32<<<dim3(4, 64), 256>>>(p_out, w1 + l * 2 * Hh * Hh, b1 + l * 2 * Hh, p_t1, 2 * Hh,
                                        nullptr, nullptr, nullptr, 0, Hh, 1,
                                        nullptr, nullptr, nullptr, nullptr);
        // w2 GEMM with fused final_combine epilogue -> g_h
        gemm_tf32<<<dim3(2, 64), 256>>>(p_t1, w2 + l * 2 * Hh * Hh, b2 + l * Hh, p_h, Hh,
                                        nullptr, nullptr, nullptr, 0, 2 * Hh, 3,
                                        p_out, p_h,
                                        bn_g + (l * 3 + 2) * Hh, bn_b + (l * 3 + 2) * Hh);
    }

    // output projection -> [4096, 2]
    out_proj<<<Nn / 8, 256>>>(p_h, w_out, b_out, out);
}

// round 14
// speedup vs baseline: 1.2818x; 1.0970x over previous
#include <cuda_runtime.h>
#include <math.h>

#define Nn 4096
#define Ee 262144
#define IND 64
#define Hh 128
#define NHEADS 4
#define DHd 32
#define Ll 2
#define KSPLIT 4
#define NQH (Nn * NHEADS)
#define FLASHBLK ((Nn / 64) * NHEADS * KSPLIT)   // 1024
#define NTILES ((Nn / KSPLIT) / 64)              // 16
#define LOG2E 1.4426950408889634f

typedef unsigned long long ull;

// ---------------- scratch (static device globals; no allocation) -------------
__device__ float g_h[Nn*Hh];
__device__ float g_xp[Nn*Hh];
__device__ float g_alsd[Nn*8];          // log2-scaled: [n][0..3]=als, [4..7]=ald
__device__ float g_asv[Ll*2*NHEADS*Hh]; // log2-scaled attention vectors
__device__ unsigned g_mxals[Ll*NHEADS]; // ordered-uint per-head global max of als
__device__ float g_hloc[Nn*Hh];
__device__ float g_qkv[Nn*3*Hh];        // K/V parts tf32-pre-rounded
__device__ float g_attn[Nn*Hh];
__device__ float g_out[Nn*Hh];
__device__ float g_t1[Nn*2*Hh];
// flash split-K partials
__device__ float g_pm[KSPLIT*NQH];
__device__ float g_pl[KSPLIT*NQH];
__device__ float g_pacc[KSPLIT*NQH*DHd];
__device__ int   g_tick[256];           // zero-init; self-resetting
// CSR
__device__ int g_cnt[Nn];
__device__ int g_cursor[Nn];
__device__ int g_rowptr[Nn+1];
__device__ int g_srcs[Ee];

__device__ __forceinline__ float bn_scale(float g) { return g * rsqrtf(1.0f + 1e-5f); }

__device__ __forceinline__ float ex2(float x) {
    float r; asm("ex2.approx.f32 %0,%1;" : "=f"(r) : "f"(x)); return r;
}
__device__ __forceinline__ void cpa16(void* sdst, const void* gsrc) {
    unsigned s = (unsigned)__cvta_generic_to_shared(sdst);
    asm volatile("cp.async.cg.shared.global [%0],[%1],16;" :: "r"(s), "l"(gsrc));
}
// monotone float<->uint ordering for atomicMax
__device__ __forceinline__ unsigned oenc(float f) {
    unsigned u = __float_as_uint(f);
    return (u & 0x80000000u) ? ~u : (u | 0x80000000u);
}
__device__ __forceinline__ float odec(unsigned k) {
    unsigned u = (k & 0x80000000u) ? (k & 0x7fffffffu) : ~k;
    return __uint_as_float(u);
}

// ---- tf32 helpers ----
__device__ __forceinline__ unsigned tf32u(float f) {
    unsigned r; asm("cvt.rna.tf32.f32 %0,%1;" : "=r"(r) : "f"(f)); return r;
}
__device__ __forceinline__ float tf32f(float f) {
    return __uint_as_float(tf32u(f));
}
__device__ __forceinline__ void mma_tf32(float* d, const unsigned* a, unsigned b0, unsigned b1) {
    asm volatile(
        "mma.sync.aligned.m16n8k8.row.col.f32.tf32.tf32.f32 "
        "{%0,%1,%2,%3},{%4,%5,%6,%7},{%8,%9},{%0,%1,%2,%3};"
        : "+f"(d[0]), "+f"(d[1]), "+f"(d[2]), "+f"(d[3])
        : "r"(a[0]), "r"(a[1]), "r"(a[2]), "r"(a[3]), "r"(b0), "r"(b1));
}

// ---------------- tf32 GEMM core (64x64 tile, cp.async double-buffered) ------
// mode 0: none  1: relu  4: none + tf32-round C2 outputs
// mode 2: C1 = epA + (acc+bias + epH) * bn_scale(epG) + epB
// mode 3: C1 = max((epA + acc+bias) * bn_scale(epG) + epB + epH, 0)
__device__ __forceinline__ void gemm_core(
        float (*As)[64][36], float (*Bs)[64][36], int bx, int by,
        const float* __restrict__ A,
        const float* __restrict__ B1, const float* __restrict__ bias1,
        float* __restrict__ C1, int M1,
        const float* __restrict__ B2, const float* __restrict__ bias2,
        float* __restrict__ C2, int M2,
        int K, int mode,
        const float* __restrict__ epA, const float* __restrict__ epH,
        const float* __restrict__ epG, const float* __restrict__ epB) {
    const int t = threadIdx.x;
    const int w = t >> 5, lane = t & 31;
    const int gi = lane >> 2, li = lane & 3;
    const int wr = w >> 2, wc = w & 3;
    const int r0 = by * 64;
    const int c0 = bx * 64;
    const int row_s = t >> 3;
    const int kq4 = (t & 7) * 4;

    float o[2][2][4];
    #pragma unroll
    for (int mt = 0; mt < 2; mt++)
        #pragma unroll
        for (int nt = 0; nt < 2; nt++)
            #pragma unroll
            for (int i = 0; i < 4; i++) o[mt][nt][i] = 0.0f;

    auto stage = [&](int kc, int buf) {
        #pragma unroll
        for (int i = 0; i < 2; i++) {
            int row = row_s + i * 32;
            cpa16(&As[buf][row][kq4], &A[(size_t)(r0 + row) * K + kc + kq4]);
            int cc = c0 + row;
            const float* Brow = (cc < M1) ? (B1 + (size_t)cc * K)
                                          : (B2 + (size_t)(cc - M1) * K);
            cpa16(&Bs[buf][row][kq4], &Brow[kc + kq4]);
        }
        asm volatile("cp.async.commit_group;");
    };

    const int nc = K >> 5;
    stage(0, 0);
    for (int ci = 0; ci < nc; ci++) {
        int buf = ci & 1;
        if (ci + 1 < nc) {
            stage((ci + 1) << 5, buf ^ 1);
            asm volatile("cp.async.wait_group 1;");
        } else {
            asm volatile("cp.async.wait_group 0;");
        }
        __syncthreads();
        #pragma unroll
        for (int k8 = 0; k8 < 32; k8 += 8) {
            unsigned a[2][4];
            #pragma unroll
            for (int mt = 0; mt < 2; mt++) {
                int row = wr * 32 + mt * 16;
                a[mt][0] = tf32u(As[buf][row + gi    ][k8 + li]);
                a[mt][1] = tf32u(As[buf][row + gi + 8][k8 + li]);
                a[mt][2] = tf32u(As[buf][row + gi    ][k8 + li + 4]);
                a[mt][3] = tf32u(As[buf][row + gi + 8][k8 + li + 4]);
            }
            unsigned b[2][2];
            #pragma unroll
            for (int nt = 0; nt < 2; nt++) {
                int col = wc * 16 + nt * 8;
                b[nt][0] = tf32u(Bs[buf][col + gi][k8 + li]);
                b[nt][1] = tf32u(Bs[buf][col + gi][k8 + li + 4]);
            }
            #pragma unroll
            for (int mt = 0; mt < 2; mt++)
                #pragma unroll
                for (int nt = 0; nt < 2; nt++)
                    mma_tf32(o[mt][nt], a[mt], b[nt][0], b[nt][1]);
        }
        __syncthreads();
    }

    #pragma unroll
    for (int nt = 0; nt < 2; nt++) {
        int c = c0 + wc * 16 + nt * 8 + 2 * li;
        const float* bias; float* Cp; int ld, cc;
        bool isC2 = (c >= M1);
        if (!isC2) { bias = bias1; Cp = C1; ld = M1; cc = c; }
        else       { bias = bias2; Cp = C2; ld = M2; cc = c - M1; }
        float b0v = bias ? bias[cc] : 0.0f;
        float b1v = bias ? bias[cc + 1] : 0.0f;
        float gs0 = 0.f, gs1 = 0.f, gb0 = 0.f, gb1 = 0.f;
        if (mode == 2 || mode == 3) {
            gs0 = bn_scale(epG[c]); gs1 = bn_scale(epG[c + 1]);
            gb0 = epB[c]; gb1 = epB[c + 1];
        }
        #pragma unroll
        for (int mt = 0; mt < 2; mt++) {
            #pragma unroll
            for (int half = 0; half < 2; half++) {
                int r = r0 + wr * 32 + mt * 16 + gi + half * 8;
                float v0 = o[mt][nt][half * 2]     + b0v;
                float v1 = o[mt][nt][half * 2 + 1] + b1v;
                if (mode == 1) { v0 = fmaxf(v0, 0.f); v1 = fmaxf(v1, 0.f); }
                else if (mode == 2) {
                    float2 ea = *(const float2*)&epA[(size_t)r * ld + cc];
                    float2 eh = *(const float2*)&epH[(size_t)r * ld + cc];
                    v0 = ea.x + (v0 + eh.x) * gs0 + gb0;
                    v1 = ea.y + (v1 + eh.y) * gs1 + gb1;
                } else if (mode == 3) {
                    float2 ea = *(const float2*)&epA[(size_t)r * ld + cc];
                    float2 eh = *(const float2*)&epH[(size_t)r * ld + cc];
                    v0 = fmaxf((ea.x + v0) * gs0 + gb0 + eh.x, 0.f);
                    v1 = fmaxf((ea.y + v1) * gs1 + gb1 + eh.y, 0.f);
                } else if (mode == 4 && isC2) {
                    v0 = tf32f(v0); v1 = tf32f(v1);   // pre-round K/V for flash
                }
                *(float2*)&Cp[(size_t)r * ld + cc] = make_float2(v0, v1);
            }
        }
    }
}

// standalone tf32 GEMM
__global__ void __launch_bounds__(256) gemm_tf32(
        const float* __restrict__ A,
        const float* __restrict__ B1, const float* __restrict__ bias1,
        float* __restrict__ C1, int M1,
        const float* __restrict__ B2, const float* __restrict__ bias2,
        float* __restrict__ C2, int M2,
        int K, int mode,
        const float* __restrict__ epA, const float* __restrict__ epH,
        const float* __restrict__ epG, const float* __restrict__ epB) {
    __shared__ float As[2][64][36];
    __shared__ float Bs[2][64][36];
    gemm_core(As, Bs, blockIdx.x, blockIdx.y, A, B1, bias1, C1, M1,
              B2, bias2, C2, M2, K, mode, epA, epH, epG, epB);
}

// fused: [0,128) input GEMM, [128,192) CSR hist, [192,200) asv precompute
__global__ void __launch_bounds__(256) fused_ingemm_hist(
        const int* __restrict__ ei,
        const float* __restrict__ x,
        const float* __restrict__ w_in, const float* __restrict__ b_in,
        float* __restrict__ C,
        const float* __restrict__ w_gat,
        const float* __restrict__ att_src, const float* __restrict__ att_dst) {
    __shared__ __align__(16) char smbuf[2 * 64 * 36 * 4 * 2];
    const int t = threadIdx.x;
    if (blockIdx.x < 128) {
        float (*As)[64][36] = (float(*)[64][36])smbuf;
        float (*Bs)[64][36] = (float(*)[64][36])(smbuf + 2 * 64 * 36 * 4);
        gemm_core(As, Bs, blockIdx.x & 1, blockIdx.x >> 1, x, w_in, b_in, C, Hh,
                  nullptr, nullptr, nullptr, 0, IND, 1,
                  nullptr, nullptr, nullptr, nullptr);
    } else if (blockIdx.x < 192) {
        int* hist = (int*)smbuf;
        for (int i = t; i < Nn; i += 256) hist[i] = 0;
        __syncthreads();
        const int base = (blockIdx.x - 128) * 4096;
        #pragma unroll 4
        for (int i = t; i < 4096; i += 256)
            atomicAdd(&hist[ei[Ee + base + i]], 1);
        __syncthreads();
        for (int i = t; i < Nn; i += 256) {
            int v = hist[i];
            if (v) atomicAdd(&g_cnt[i], v);
        }
    } else {
        // asv[l][sd][h][c] = log2e * sum_d a[l][h][d] * w_gat[l][(h*32+d)][c]
        int i = (blockIdx.x - 192) * 256 + t;          // 0..2047
        int c  = i & 127;
        int h  = (i >> 7) & 3;
        int sd = (i >> 9) & 1;
        int l  = i >> 10;
        const float* av = (sd == 0 ? att_src : att_dst) + l * Hh + h * DHd;
        const float* wg = w_gat + (size_t)l * Hh * Hh + (size_t)(h * DHd) * Hh + c;
        float s = 0.0f;
        #pragma unroll
        for (int d = 0; d < DHd; d++)
            s = fmaf(av[d], wg[(size_t)d * Hh], s);
        g_asv[i] = s * LOG2E;
    }
}

// fused per-layer projection:
//  [0,512): GAT+QKV GEMM (mode 4: qkv tf32-rounded)
//  [512,640): alsd mat-vec (+per-head als max)   [640,...): scatter (l==0)
__global__ void __launch_bounds__(256) fused_proj(
        const int* __restrict__ ei, int do_scatter, int layer,
        const float* __restrict__ A,
        const float* __restrict__ w_gat,
        const float* __restrict__ w_qkv, const float* __restrict__ b_qkv,
        float* __restrict__ Cxp, float* __restrict__ Cqkv) {
    __shared__ float As[2][64][36];
    __shared__ float Bs[2][64][36];
    if (blockIdx.x < 512) {
        gemm_core(As, Bs, blockIdx.x & 7, blockIdx.x >> 3, A,
                  w_gat, nullptr, Cxp, Hh,
                  w_qkv, b_qkv, Cqkv, 3 * Hh,
                  Hh, 4, nullptr, nullptr, nullptr, nullptr);
    } else if (blockIdx.x < 640) {
        int i = (blockIdx.x - 512) * 256 + threadIdx.x;   // 0..32767
        int j = i & 7;
        int n = i >> 3;
        const float4* hr = (const float4*)&A[(size_t)n * Hh];
        int sd = j >> 2, h = j & 3;
        const float4* av = (const float4*)&g_asv[((layer * 2 + sd) * NHEADS + h) * Hh];
        float s = 0.0f;
        #pragma unroll
        for (int q = 0; q < 32; q++) {
            float4 a = hr[q], b = av[q];
            s += a.x*b.x + a.y*b.y + a.z*b.z + a.w*b.w;
        }
        g_alsd[n * 8 + j] = s;
        float m = s;
        m = fmaxf(m, __shfl_xor_sync(0xffffffffu, m, 8));
        m = fmaxf(m, __shfl_xor_sync(0xffffffffu, m, 16));
        int lane = threadIdx.x & 31;
        if (sd == 0 && lane < 8)
            atomicMax(&g_mxals[layer * NHEADS + h], oenc(m));
    } else if (do_scatter) {
        int e = (blockIdx.x - 640) * 256 + threadIdx.x;
        if (e < Ee) {
            int d = ei[Ee + e];
            int pos = atomicAdd(&g_cursor[d], 1);
            g_srcs[pos] = ei[e];
        }
    }
}

__global__ void csr_scan() {
    __shared__ int sm[1024];
    int t = threadIdx.x;
    int b = t * 4;
    int c0 = g_cnt[b], c1 = g_cnt[b+1], c2 = g_cnt[b+2], c3 = g_cnt[b+3];
    int s1 = c0 + c1, s2 = s1 + c2, s3 = s2 + c3;
    sm[t] = s3;
    __syncthreads();
    for (int off = 1; off < 1024; off <<= 1) {
        int v = (t >= off) ? sm[t - off] : 0;
        __syncthreads();
        sm[t] += v;
        __syncthreads();
    }
    int excl = sm[t] - s3;
    g_rowptr[b]   = excl;
    g_rowptr[b+1] = excl + c0;
    g_rowptr[b+2] = excl + s1;
    g_rowptr[b+3] = excl + s2;
    g_cursor[b]   = excl;
    g_cursor[b+1] = excl + c0;
    g_cursor[b+2] = excl + s1;
    g_cursor[b+3] = excl + s2;
    if (t == 1023) g_rowptr[Nn] = sm[1023];
}

// ---------------- output projection: warp per node, M=2 ----------------------
__global__ void __launch_bounds__(256) out_proj(
        const float* __restrict__ hsrc, const float* __restrict__ w_out,
        const float* __restrict__ b_out, float* __restrict__ out) {
    const int warp = threadIdx.x >> 5, lane = threadIdx.x & 31;
    const int n = blockIdx.x * 8 + warp;
    float4 h4 = *(const float4*)&hsrc[(size_t)n * Hh + lane * 4];
    float4 w0 = *(const float4*)&w_out[lane * 4];
    float4 w1 = *(const float4*)&w_out[Hh + lane * 4];
    float s0 = h4.x*w0.x + h4.y*w0.y + h4.z*w0.z + h4.w*w0.w;
    float s1 = h4.x*w1.x + h4.y*w1.y + h4.z*w1.z + h4.w*w1.w;
    #pragma unroll
    for (int off = 16; off > 0; off >>= 1) {
        s0 += __shfl_xor_sync(0xffffffffu, s0, off);
        s1 += __shfl_xor_sync(0xffffffffu, s1, off);
    }
    if (lane == 0) {
        out[n * 2]     = s0 + b_out[0];
        out[n * 2 + 1] = s1 + b_out[1];
    }
}

__device__ __forceinline__ float leaky(float x) { return x >= 0.0f ? x : 0.2f * x; }

struct FlashSmem {
    float Ks[64][36];
    float Vs[64][40];
    float Ps[4][16][68];   // 64 cols + 4 pad — P is 16x64 per warp (do NOT shrink)
};

// ---------------- FAT kernel: blocks [0,1024) = flash, [1024,5120) = GAT -----
__global__ void __launch_bounds__(128) gat_flash(
        int layer,
        const float* __restrict__ bias, const float* __restrict__ g0,
        const float* __restrict__ b0) {
    __shared__ FlashSmem sm;
    __shared__ int s_last;
    const int t = threadIdx.x;
    const float NEGINF = -__int_as_float(0x7f800000);

    if (blockIdx.x < FLASHBLK) {
        const int fb = blockIdx.x;
        const int qt = fb & 63;
        const int hd = (fb >> 6) & 3;
        const int sp = fb >> 8;
        const int w = t >> 5, lane = t & 31;
        const int gi = lane >> 2, li = lane & 3;
        const int q0 = qt * 64 + w * 16;
        const int kbase = sp * (Nn / KSPLIT);

        unsigned qa[4][4];
        {
            // 1/sqrt(32) * log2(e): scores land in log2 domain
            const float scq = 0.17677669529663687f * LOG2E;
            #pragma unroll
            for (int ks = 0; ks < 4; ks++) {
                int c = hd * 32 + ks * 8 + li;
                qa[ks][0] = tf32u(g_qkv[(q0+gi  )*384 + c] * scq);
                qa[ks][1] = tf32u(g_qkv[(q0+gi+8)*384 + c] * scq);
                qa[ks][2] = tf32u(g_qkv[(q0+gi  )*384 + c+4] * scq);
                qa[ks][3] = tf32u(g_qkv[(q0+gi+8)*384 + c+4] * scq);
            }
        }

        // K/V already tf32-rounded in g_qkv (GEMM epilogue) — direct cp.async
        auto stage_K = [&](int ti) {
            int kb = kbase + ti * 64;
            #pragma unroll
            for (int i = 0; i < 4; i++) {
                int c = t + i * 128;
                int j = c >> 3, d4 = c & 7;
                cpa16(&sm.Ks[j][d4 * 4], &g_qkv[(kb + j) * 384 + 128 + hd * 32 + d4 * 4]);
            }
            asm volatile("cp.async.commit_group;");
        };
        auto stage_V = [&](int ti) {
            int kb = kbase + ti * 64;
            #pragma unroll
            for (int i = 0; i < 4; i++) {
                int c = t + i * 128;
                int j = c >> 3, d4 = c & 7;
                cpa16(&sm.Vs[j][d4 * 4], &g_qkv[(kb + j) * 384 + 256 + hd * 32 + d4 * 4]);
            }
            asm volatile("cp.async.commit_group;");
        };

        float mxl = NEGINF, mxh = NEGINF, lsl = 0.0f, lsh = 0.0f;
        float o[4][4];
        #pragma unroll
        for (int jn = 0; jn < 4; jn++)
            #pragma unroll
            for (int i = 0; i < 4; i++) o[jn][i] = 0.0f;

        stage_K(0);
        stage_V(0);
        for (int ti = 0; ti < NTILES; ti++) {
            asm volatile("cp.async.wait_group 0;");
            __syncthreads();

            // QK from Ks
            float s[8][4];
            #pragma unroll
            for (int jk = 0; jk < 8; jk++) {
                s[jk][0] = s[jk][1] = s[jk][2] = s[jk][3] = 0.0f;
                #pragma unroll
                for (int ks = 0; ks < 4; ks++) {
                    unsigned b0v = __float_as_uint(sm.Ks[jk*8+gi][ks*8+li]);
                    unsigned b1v = __float_as_uint(sm.Ks[jk*8+gi][ks*8+li+4]);
                    mma_tf32(s[jk], qa[ks], b0v, b1v);
                }
            }
            __syncthreads();                     // Ks dead -> prefetch next K
            if (ti + 1 < NTILES) stage_K(ti + 1);

            float tml = NEGINF, tmh = NEGINF;
            #pragma unroll
            for (int jk = 0; jk < 8; jk++) {
                tml = fmaxf(tml, fmaxf(s[jk][0], s[jk][1]));
                tmh = fmaxf(tmh, fmaxf(s[jk][2], s[jk][3]));
            }
            tml = fmaxf(tml, __shfl_xor_sync(0xffffffffu, tml, 1));
            tml = fmaxf(tml, __shfl_xor_sync(0xffffffffu, tml, 2));
            tmh = fmaxf(tmh, __shfl_xor_sync(0xffffffffu, tmh, 1));
            tmh = fmaxf(tmh, __shfl_xor_sync(0xffffffffu, tmh, 2));
            float nml = fmaxf(mxl, tml), nmh = fmaxf(mxh, tmh);
            float scl = ex2(mxl - nml), sch = ex2(mxh - nmh);
            mxl = nml; mxh = nmh;
            lsl *= scl; lsh *= sch;
            #pragma unroll
            for (int jn = 0; jn < 4; jn++) {
                o[jn][0] *= scl; o[jn][1] *= scl;
                o[jn][2] *= sch; o[jn][3] *= sch;
            }
            float rsl = 0.0f, rsh = 0.0f;
            #pragma unroll
            for (int jk = 0; jk < 8; jk++) {
                float p0 = ex2(s[jk][0] - mxl), p1 = ex2(s[jk][1] - mxl);
                float p2 = ex2(s[jk][2] - mxh), p3 = ex2(s[jk][3] - mxh);
                rsl += p0 + p1; rsh += p2 + p3;
                float2 lo = make_float2(tf32f(p0), tf32f(p1));
                float2 hi = make_float2(tf32f(p2), tf32f(p3));
                *(float2*)&sm.Ps[w][gi  ][jk*8 + 2*li] = lo;
                *(float2*)&sm.Ps[w][gi+8][jk*8 + 2*li] = hi;
            }
            rsl += __shfl_xor_sync(0xffffffffu, rsl, 1);
            rsl += __shfl_xor_sync(0xffffffffu, rsl, 2);
            rsh += __shfl_xor_sync(0xffffffffu, rsh, 1);
            rsh += __shfl_xor_sync(0xffffffffu, rsh, 2);
            lsl += rsl; lsh += rsh;
            __syncwarp();
            #pragma unroll
            for (int kk = 0; kk < 8; kk++) {
                unsigned pa[4];
                pa[0] = __float_as_uint(sm.Ps[w][gi  ][kk*8 + li]);
                pa[1] = __float_as_uint(sm.Ps[w][gi+8][kk*8 + li]);
                pa[2] = __float_as_uint(sm.Ps[w][gi  ][kk*8 + li + 4]);
                pa[3] = __float_as_uint(sm.Ps[w][gi+8][kk*8 + li + 4]);
                #pragma unroll
                for (int jn = 0; jn < 4; jn++) {
                    unsigned b0v = __float_as_uint(sm.Vs[kk*8+li  ][jn*8+gi]);
                    unsigned b1v = __float_as_uint(sm.Vs[kk*8+li+4][jn*8+gi]);
                    mma_tf32(o[jn], pa, b0v, b1v);
                }
            }
            __syncthreads();                     // Vs dead -> prefetch next V
            if (ti + 1 < NTILES) stage_V(ti + 1);
        }

        const int nl = q0 + gi, nh = nl + 8;
        const int qhl = nl * 4 + hd, qhh = nh * 4 + hd;
        if (li == 0) {
            g_pm[sp * NQH + qhl] = mxl;    // log2 domain
            g_pl[sp * NQH + qhl] = lsl;
            g_pm[sp * NQH + qhh] = mxh;
            g_pl[sp * NQH + qhh] = lsh;
        }
        #pragma unroll
        for (int jn = 0; jn < 4; jn++) {
            int dh = jn * 8 + 2 * li;
            *(float2*)&g_pacc[((size_t)sp * NQH + qhl) * DHd + dh] = make_float2(o[jn][0], o[jn][1]);
            *(float2*)&g_pacc[((size_t)sp * NQH + qhh) * DHd + dh] = make_float2(o[jn][2], o[jn][3]);
        }

        // ---- fused split-K merge (log2-domain weights); tick self-resets ----
        __threadfence();
        if (t == 0) {
            int v = atomicAdd(&g_tick[(qt << 2) | hd], 1);
            s_last = (v == KSPLIT - 1);
            if (s_last) g_tick[(qt << 2) | hd] = 0;
        }
        __syncthreads();
        if (s_last) {
            for (int i = t; i < 64 * DHd; i += 128) {
                int q = i >> 5, dd = i & 31;
                int n = qt * 64 + q;
                int qh = n * 4 + hd;
                float m0 = g_pm[0*NQH+qh], m1 = g_pm[1*NQH+qh];
                float m2 = g_pm[2*NQH+qh], m3 = g_pm[3*NQH+qh];
                float M = fmaxf(fmaxf(m0, m1), fmaxf(m2, m3));
                float w0 = ex2(m0 - M), w1 = ex2(m1 - M);
                float w2 = ex2(m2 - M), w3 = ex2(m3 - M);
                float L = g_pl[0*NQH+qh]*w0 + g_pl[1*NQH+qh]*w1
                        + g_pl[2*NQH+qh]*w2 + g_pl[3*NQH+qh]*w3;
                float a = g_pacc[((size_t)0*NQH+qh)*DHd + dd] * w0
                        + g_pacc[((size_t)1*NQH+qh)*DHd + dd] * w1
                        + g_pacc[((size_t)2*NQH+qh)*DHd + dd] * w2
                        + g_pacc[((size_t)3*NQH+qh)*DHd + dd] * w3;
                g_attn[n * Hh + hd * DHd + dd] = a / L;
            }
        }
    } else {
        // ===== GAT aggregation: warp w = head w; global-max shift (no max pass)
        const int d = blockIdx.x - FLASHBLK;
        const int w = t >> 5, lane = t & 31;
        const int beg = g_rowptr[d], end = g_rowptr[d + 1];
        const float adh = g_alsd[d * 8 + 4 + w];           // log2-scaled
        const float mx = leaky(odec(g_mxals[layer * NHEADS + w]) + adh); // upper bound

        float den = 0.0f;
        float acc = 0.0f;
        const int c = w * 32 + lane;
        for (int cb = beg; cb < end; cb += 32) {
            int cnt = min(32, end - cb);
            int e = cb + lane;
            float wgt = 0.0f;
            int ssrc = 0;
            if (lane < cnt) {
                ssrc = g_srcs[e];
                wgt = ex2(leaky(g_alsd[ssrc * 8 + w] + adh) - mx);
            }
            den += wgt;
            for (int j = 0; j < cnt; j++) {
                float wj = __shfl_sync(0xffffffffu, wgt, j);
                int sj   = __shfl_sync(0xffffffffu, ssrc, j);
                acc = fmaf(wj, g_xp[sj * Hh + c], acc);
            }
        }
        #pragma unroll
        for (int off = 16; off > 0; off >>= 1)
            den += __shfl_xor_sync(0xffffffffu, den, off);

        float v = acc / (den + 1e-16f) + bias[c] + g_h[d * Hh + c];
        g_hloc[d * Hh + c] = v * bn_scale(g0[c]) + b0[c];
    }
}

// ---------------- host launch ----------------
extern "C" void kernel_launch(void* const* d_in, const int* in_sizes, int n_in,
                              void* d_out, int out_size) {
    const float* x       = (const float*)d_in[0];
    const int*   ei      = (const int*)d_in[1];
    const float* w_in    = (const float*)d_in[2];
    const float* b_in    = (const float*)d_in[3];
    const float* w_gat   = (const float*)d_in[4];
    const float* att_src = (const float*)d_in[5];
    const float* att_dst = (const float*)d_in[6];
    const float* b_gat   = (const float*)d_in[7];
    const float* w_qkv   = (const float*)d_in[8];
    const float* b_qkv   = (const float*)d_in[9];
    const float* w_o     = (const float*)d_in[10];
    const float* b_o     = (const float*)d_in[11];
    const float* bn_g    = (const float*)d_in[12];
    const float* bn_b    = (const float*)d_in[13];
    const float* w1      = (const float*)d_in[14];
    const float* b1      = (const float*)d_in[15];
    const float* w2      = (const float*)d_in[16];
    const float* b2      = (const float*)d_in[17];
    const float* w_out   = (const float*)d_in[18];
    const float* b_out   = (const float*)d_in[19];
    float* out = (float*)d_out;

    float *p_h, *p_xp, *p_qkv, *p_attn, *p_out, *p_t1, *p_hloc;
    int* p_cnt;
    cudaGetSymbolAddress((void**)&p_h,    g_h);
    cudaGetSymbolAddress((void**)&p_xp,   g_xp);
    cudaGetSymbolAddress((void**)&p_qkv,  g_qkv);
    cudaGetSymbolAddress((void**)&p_attn, g_attn);
    cudaGetSymbolAddress((void**)&p_out,  g_out);
    cudaGetSymbolAddress((void**)&p_t1,   g_t1);
    cudaGetSymbolAddress((void**)&p_hloc, g_hloc);
    cudaGetSymbolAddress((void**)&p_cnt,  g_cnt);

    // CSR count + input projection + asv precompute overlapped
    cudaMemsetAsync(p_cnt, 0, Nn * sizeof(int));
    fused_ingemm_hist<<<200, 256>>>(ei, x, w_in, b_in, p_h, w_gat, att_src, att_dst);
    csr_scan<<<1, 1024>>>();

    for (int l = 0; l < Ll; l++) {
        // projection: GAT+QKV GEMM (qkv tf32-rounded) + alsd (+ scatter l==0)
        int nblk = 640 + (l == 0 ? Ee / 256 : 0);
        fused_proj<<<nblk, 256>>>(ei, l == 0, l, p_h,
                                  w_gat + l * Hh * Hh,
                                  w_qkv + l * 3 * Hh * Hh, b_qkv + l * 3 * Hh,
                                  p_xp, p_qkv);

        // FAT kernel: flash attention (split-K merge fused) + GAT aggregation
        gat_flash<<<FLASHBLK + Nn, 128>>>(l, b_gat + l * Hh,
                                          bn_g + (l * 3 + 0) * Hh, bn_b + (l * 3 + 0) * Hh);

        // w_o GEMM with fused combine_att epilogue -> g_out
        gemm_tf32<<<dim3(2, 64), 256>>>(p_attn, w_o + l * Hh * Hh, b_o + l * Hh, p_out, Hh,
                                        nullptr, nullptr, nullptr, 0, Hh, 2,
                                        p_hloc, p_h,
                                        bn_g + (l * 3 + 1) * Hh, bn_b + (l * 3 + 1) * Hh);

        // MLP
        gemm_tf32<<<dim3(4, 64), 256>>>(p_out, w1 + l * 2 * Hh * Hh, b1 + l * 2 * Hh, p_t1, 2 * Hh,
                                        nullptr, nullptr, nullptr, 0, Hh, 1,
                                        nullptr, nullptr, nullptr, nullptr);
        // w2 GEMM with fused final_combine epilogue -> g_h
        gemm_tf32<<<dim3(2, 64), 256>>>(p_t1, w2 + l * 2 * Hh * Hh, b2 + l * Hh, p_h, Hh,
                                        nullptr, nullptr, nullptr, 0, 2 * Hh, 3,
                                        p_out, p_h,
                                        bn_g + (l * 3 + 2) * Hh, bn_b + (l * 3 + 2) * Hh);
    }

    // output projection -> [4096, 2]
    out_proj<<<Nn / 8, 256>>>(p_h, w_out, b_out, out);
}